// round 3
// baseline (speedup 1.0000x reference)
#include <cuda_runtime.h>
#include <cstddef>

#define N_NODES   60000
#define N_EDGES   240000
#define WIDTH     256
#define DIM_HEAD  32
#define NUM_HEAD  8
#define TILE      32
#define PITCH     260   // floats; 16B-aligned rows, (4n+k)%32 bank pattern

__device__ float g_agg[(size_t)N_NODES * WIDTH];

__device__ __forceinline__ float sp(float x) {
    // jax.nn.softplus: max(x,0) + log1p(exp(-|x|))
    return fmaxf(x, 0.f) + log1pf(expf(-fabsf(x)));
}

__device__ __forceinline__ float wsum(float v) {
#pragma unroll
    for (int o = 16; o; o >>= 1) v += __shfl_xor_sync(0xffffffffu, v, o);
    return v;
}

// ============================================================================
// Zero the aggregation scratch
// ============================================================================
__global__ void zero_agg_kernel() {
    size_t n4 = (size_t)N_NODES * WIDTH / 4;
    float4* p = (float4*)g_agg;
    for (size_t i = (size_t)blockIdx.x * blockDim.x + threadIdx.x; i < n4;
         i += (size_t)gridDim.x * blockDim.x)
        p[i] = make_float4(0.f, 0.f, 0.f, 0.f);
}

// ============================================================================
// Edge kernel: per 32-edge tile, compute
//   emb  = sum(emb_edge[attr]) + moa(diff) @ elec_lin                [32]
//   msg  = x[i0] + x[i1]                                             [256]
//   out  = msg @ lin_pre + ((msg @ lora_down) * emb) @ lora_up       [256]
//   atomicAdd into g_agg[i1]
// ============================================================================
__global__ __launch_bounds__(256) void edge_kernel(
    const float* __restrict__ x,
    const int*   __restrict__ edge_idx,
    const int*   __restrict__ edge_attr,
    const float* __restrict__ node_elec,
    const float* __restrict__ lora_down,
    const float* __restrict__ lora_up,
    const float* __restrict__ emb_edge,
    const float* __restrict__ moa_w,
    const float* __restrict__ moa_s,
    const float* __restrict__ elec_lin,
    const float* __restrict__ lin_pre)
{
    __shared__ float msg_s[TILE][PITCH];
    __shared__ float emb_s[TILE][33];
    __shared__ float t2_s [TILE][33];
    __shared__ int   s_i0[TILE], s_i1[TILE];

    const int tid = threadIdx.x;
    const int eb  = blockIdx.x * TILE;

    if (tid < TILE) {
        s_i0[tid] = edge_idx[eb + tid];
        s_i1[tid] = edge_idx[N_EDGES + eb + tid];
    }
    __syncthreads();

    // --- stage msg = x[i0] + x[i1], row-major [e][k] ---
    {
        const int e  = tid >> 3;
        const int c0 = (tid & 7) * 4;
        const float4* r0 = (const float4*)(x + (size_t)s_i0[e] * WIDTH);
        const float4* r1 = (const float4*)(x + (size_t)s_i1[e] * WIDTH);
#pragma unroll
        for (int it = 0; it < 8; it++) {
            int c = c0 + it * 32;
            float4 a = __ldg(&r0[c >> 2]);
            float4 b = __ldg(&r1[c >> 2]);
            *(float4*)&msg_s[e][c] =
                make_float4(a.x + b.x, a.y + b.y, a.z + b.z, a.w + b.w);
        }
    }

    // --- edge embedding: 4 edges per warp, lane = dim ---
    {
        const int wid = tid >> 5, lane = tid & 31;
        float w0 = sp(moa_w[lane]);
        float w1 = sp(moa_w[32 + lane]);
        w0 /= wsum(w0);
        w1 /= wsum(w1);
        const float s0  = sp(moa_s[lane]);
        const float s1  = sp(moa_s[32 + lane]);
        const float el0 = elec_lin[lane];
        const float el1 = elec_lin[32 + lane];
#pragma unroll
        for (int i = 0; i < 4; i++) {
            int e  = wid * 4 + i;
            int i0 = s_i0[e], i1 = s_i1[e];
            float d0 = node_elec[2 * i0]     - node_elec[2 * i1];
            float d1 = node_elec[2 * i0 + 1] - node_elec[2 * i1 + 1];
            float m0 = wsum(tanhf(d0 * s0) * w0);
            float m1 = wsum(tanhf(d1 * s1) * w1);
            int ge = eb + e;
            int a0 = edge_attr[3 * ge], a1 = edge_attr[3 * ge + 1], a2 = edge_attr[3 * ge + 2];
            emb_s[e][lane] = emb_edge[a0 * 32 + lane] + emb_edge[a1 * 32 + lane] +
                             emb_edge[a2 * 32 + lane] + m0 * el0 + m1 * el1;
        }
    }
    __syncthreads();

    // --- t2 = (msg @ lora_down) * emb   [32 e][32 d] ---
    {
        const int e = tid >> 3;
        const int d = (tid & 7) * 4;
        float4 acc = make_float4(0.f, 0.f, 0.f, 0.f);
#pragma unroll 4
        for (int k = 0; k < WIDTH; k++) {
            float  m  = msg_s[e][k];
            float4 ld = __ldg((const float4*)(lora_down + k * 32 + d));
            acc.x += m * ld.x; acc.y += m * ld.y;
            acc.z += m * ld.z; acc.w += m * ld.w;
        }
        t2_s[e][d + 0] = acc.x * emb_s[e][d + 0];
        t2_s[e][d + 1] = acc.y * emb_s[e][d + 1];
        t2_s[e][d + 2] = acc.z * emb_s[e][d + 2];
        t2_s[e][d + 3] = acc.w * emb_s[e][d + 3];
    }
    __syncthreads();

    // --- main GEMM: out[e][f] = sum_k msg[e][k]*lin_pre[k][f]
    //                          + sum_d t2[e][d]*lora_up[d][f], then scatter ---
    {
        const int f  = (tid & 63) * 4;
        const int e0 = (tid >> 6) * 8;
        float4 acc[8];
#pragma unroll
        for (int j = 0; j < 8; j++) acc[j] = make_float4(0.f, 0.f, 0.f, 0.f);

#pragma unroll 2
        for (int k = 0; k < WIDTH; k++) {
            float4 w4 = __ldg((const float4*)(lin_pre + k * WIDTH + f));
#pragma unroll
            for (int j = 0; j < 8; j++) {
                float m = msg_s[e0 + j][k];
                acc[j].x += m * w4.x; acc[j].y += m * w4.y;
                acc[j].z += m * w4.z; acc[j].w += m * w4.w;
            }
        }
#pragma unroll 2
        for (int d = 0; d < DIM_HEAD; d++) {
            float4 u4 = __ldg((const float4*)(lora_up + d * WIDTH + f));
#pragma unroll
            for (int j = 0; j < 8; j++) {
                float m = t2_s[e0 + j][d];
                acc[j].x += m * u4.x; acc[j].y += m * u4.y;
                acc[j].z += m * u4.z; acc[j].w += m * u4.w;
            }
        }
#pragma unroll
        for (int j = 0; j < 8; j++) {
            float* p = g_agg + (size_t)s_i1[e0 + j] * WIDTH + f;
            atomicAdd(p + 0, acc[j].x);
            atomicAdd(p + 1, acc[j].y);
            atomicAdd(p + 2, acc[j].z);
            atomicAdd(p + 3, acc[j].w);
        }
    }
}

// ============================================================================
// Node kernel: per 32-node tile
//   U = agg@gate_lin, V = agg@value_lin  (per-head RMS norm, gate bias)
//   gg = un@gate_kernel[h], vv = vn@value_kernel[h]
//   a  = clip(softplus(gg + act_bias)); out_h = (a*vv)@post_kernel[h]
// ============================================================================
__global__ __launch_bounds__(256) void node_kernel(
    const int*   __restrict__ deg,
    const float* __restrict__ emb_deg,
    const float* __restrict__ gate_lin,
    const float* __restrict__ gate_kernel,
    const float* __restrict__ value_lin,
    const float* __restrict__ value_kernel,
    const float* __restrict__ act_bias,
    const float* __restrict__ post_kernel,
    float*       __restrict__ out)
{
    extern __shared__ float sm[];
    float* agg_s = sm;                   // [32][PITCH]
    float* u_s   = sm + 32 * PITCH;      // [32][PITCH]
    float* v_s   = sm + 2 * 32 * PITCH;  // [32][PITCH]
    float* avv_s = sm;                   // reuse agg region, pitch 132

    const int tid = threadIdx.x;
    const int nb  = blockIdx.x * TILE;

    // --- load agg tile ---
    {
        const int n  = tid >> 3;
        const int c0 = (tid & 7) * 4;
        const float4* r = (const float4*)(g_agg + (size_t)(nb + n) * WIDTH);
#pragma unroll
        for (int it = 0; it < 8; it++) {
            int c = c0 + it * 32;
            *(float4*)&agg_s[n * PITCH + c] = r[c >> 2];
        }
    }
    __syncthreads();

    // --- U and V (two passes of 256x256 GEMM) ---
    {
        const int f  = (tid & 63) * 4;
        const int n0 = (tid >> 6) * 8;
#pragma unroll 1
        for (int pass = 0; pass < 2; pass++) {
            const float* W  = pass ? value_lin : gate_lin;
            float* Odst     = pass ? v_s : u_s;
            float4 acc[8];
#pragma unroll
            for (int j = 0; j < 8; j++) acc[j] = make_float4(0.f, 0.f, 0.f, 0.f);
#pragma unroll 2
            for (int k = 0; k < WIDTH; k++) {
                float4 w4 = __ldg((const float4*)(W + k * WIDTH + f));
#pragma unroll
                for (int j = 0; j < 8; j++) {
                    float m = agg_s[(n0 + j) * PITCH + k];
                    acc[j].x += m * w4.x; acc[j].y += m * w4.y;
                    acc[j].z += m * w4.z; acc[j].w += m * w4.w;
                }
            }
#pragma unroll
            for (int j = 0; j < 8; j++)
                *(float4*)&Odst[(n0 + j) * PITCH + f] = acc[j];
        }
    }
    __syncthreads();

    // --- per-(node,head) RMS norm; gate path adds bias and /sqrt(2) ---
    {
        const int n = tid & 31, h = tid >> 5;
        const int gn = nb + n;
        const int dd = deg[gn];
        const float inv_s2 = 0.70710678118654752440f;

        float4 uu[8];
        float ss = 0.f;
#pragma unroll
        for (int i = 0; i < 8; i++) {
            uu[i] = *(float4*)&u_s[n * PITCH + h * 32 + 4 * i];
            ss += uu[i].x * uu[i].x + uu[i].y * uu[i].y +
                  uu[i].z * uu[i].z + uu[i].w * uu[i].w;
        }
        float rinv = rsqrtf(ss * (1.f / 32.f) + 1e-6f);
#pragma unroll
        for (int i = 0; i < 8; i++) {
            float4 b = __ldg((const float4*)(emb_deg + dd * 256 + h * 32 + 4 * i));
            float4 o;
            o.x = (uu[i].x * rinv + b.x) * inv_s2;
            o.y = (uu[i].y * rinv + b.y) * inv_s2;
            o.z = (uu[i].z * rinv + b.z) * inv_s2;
            o.w = (uu[i].w * rinv + b.w) * inv_s2;
            *(float4*)&u_s[n * PITCH + h * 32 + 4 * i] = o;
        }

        float4 vv4[8];
        float ssv = 0.f;
#pragma unroll
        for (int i = 0; i < 8; i++) {
            vv4[i] = *(float4*)&v_s[n * PITCH + h * 32 + 4 * i];
            ssv += vv4[i].x * vv4[i].x + vv4[i].y * vv4[i].y +
                   vv4[i].z * vv4[i].z + vv4[i].w * vv4[i].w;
        }
        float rinvv = rsqrtf(ssv * (1.f / 32.f) + 1e-6f);
#pragma unroll
        for (int i = 0; i < 8; i++) {
            float4 o;
            o.x = vv4[i].x * rinvv; o.y = vv4[i].y * rinvv;
            o.z = vv4[i].z * rinvv; o.w = vv4[i].w * rinvv;
            *(float4*)&v_s[n * PITCH + h * 32 + 4 * i] = o;
        }
    }
    __syncthreads();

    const float CLIP_LO = 0.22360679774997896f;   // 1/sqrt(20)
    const float CLIP_HI = 4.47213595499957939f;   // sqrt(20)

    // --- per-head gate/value GEMMs + activation + post GEMM ---
#pragma unroll 1
    for (int h = 0; h < NUM_HEAD; h++) {
        {
            const int f2 = (tid & 31) * 4;
            const int n0 = (tid >> 5) * 4;
            const float* GK = gate_kernel  + h * 32 * 128;
            const float* VK = value_kernel + h * 32 * 128;
            float4 ag[4], av[4];
#pragma unroll
            for (int j = 0; j < 4; j++) {
                ag[j] = make_float4(0.f, 0.f, 0.f, 0.f);
                av[j] = make_float4(0.f, 0.f, 0.f, 0.f);
            }
#pragma unroll 2
            for (int d = 0; d < 32; d++) {
                float4 g4 = __ldg((const float4*)(GK + d * 128 + f2));
                float4 v4 = __ldg((const float4*)(VK + d * 128 + f2));
#pragma unroll
                for (int j = 0; j < 4; j++) {
                    float ub = u_s[(n0 + j) * PITCH + h * 32 + d];
                    float vb = v_s[(n0 + j) * PITCH + h * 32 + d];
                    ag[j].x += ub * g4.x; ag[j].y += ub * g4.y;
                    ag[j].z += ub * g4.z; ag[j].w += ub * g4.w;
                    av[j].x += vb * v4.x; av[j].y += vb * v4.y;
                    av[j].z += vb * v4.z; av[j].w += vb * v4.w;
                }
            }
            float4 ab = __ldg((const float4*)(act_bias + h * 128 + f2));
#pragma unroll
            for (int j = 0; j < 4; j++) {
                float4 o;
                o.x = fminf(fmaxf(sp(ag[j].x + ab.x), CLIP_LO), CLIP_HI) * av[j].x;
                o.y = fminf(fmaxf(sp(ag[j].y + ab.y), CLIP_LO), CLIP_HI) * av[j].y;
                o.z = fminf(fmaxf(sp(ag[j].z + ab.z), CLIP_LO), CLIP_HI) * av[j].z;
                o.w = fminf(fmaxf(sp(ag[j].w + ab.w), CLIP_LO), CLIP_HI) * av[j].w;
                *(float4*)&avv_s[(n0 + j) * 132 + f2] = o;
            }
        }
        __syncthreads();
        {
            const int d2 = (tid & 7) * 4;
            const int n  = tid >> 3;
            const float* PK = post_kernel + h * 128 * 32;
            float4 acc = make_float4(0.f, 0.f, 0.f, 0.f);
#pragma unroll 4
            for (int f2 = 0; f2 < 128; f2++) {
                float4 p4 = __ldg((const float4*)(PK + f2 * 32 + d2));
                float  a  = avv_s[n * 132 + f2];
                acc.x += a * p4.x; acc.y += a * p4.y;
                acc.z += a * p4.z; acc.w += a * p4.w;
            }
            *(float4*)&out[(size_t)(nb + n) * WIDTH + h * 32 + d2] = acc;
        }
        __syncthreads();
    }
}

// ============================================================================
// Launch
// ============================================================================
extern "C" void kernel_launch(void* const* d_in, const int* in_sizes, int n_in,
                              void* d_out, int out_size) {
    const float* x            = (const float*)d_in[0];
    const int*   deg          = (const int*)  d_in[1];
    const int*   edge_idx     = (const int*)  d_in[2];
    const int*   edge_attr    = (const int*)  d_in[3];
    const float* node_elec    = (const float*)d_in[4];
    const float* lora_down    = (const float*)d_in[5];
    const float* lora_up      = (const float*)d_in[6];
    const float* emb_edge     = (const float*)d_in[7];
    const float* moa_w        = (const float*)d_in[8];
    const float* moa_s        = (const float*)d_in[9];
    const float* elec_lin     = (const float*)d_in[10];
    const float* emb_deg      = (const float*)d_in[11];
    const float* lin_pre      = (const float*)d_in[12];
    const float* gate_lin     = (const float*)d_in[13];
    const float* gate_kernel  = (const float*)d_in[14];
    const float* value_lin    = (const float*)d_in[15];
    const float* value_kernel = (const float*)d_in[16];
    const float* act_bias     = (const float*)d_in[17];
    const float* post_kernel  = (const float*)d_in[18];
    float* out = (float*)d_out;

    zero_agg_kernel<<<2048, 256>>>();

    edge_kernel<<<N_EDGES / TILE, 256>>>(
        x, edge_idx, edge_attr, node_elec,
        lora_down, lora_up, emb_edge, moa_w, moa_s, elec_lin, lin_pre);

    size_t nsm = (size_t)3 * 32 * PITCH * sizeof(float);  // 99840 B
    cudaFuncSetAttribute(node_kernel,
                         cudaFuncAttributeMaxDynamicSharedMemorySize, (int)nsm);
    node_kernel<<<N_NODES / TILE, 256, nsm>>>(
        deg, emb_deg, gate_lin, gate_kernel, value_lin, value_kernel,
        act_bias, post_kernel, out);
}

// round 4
// speedup vs baseline: 1.4491x; 1.4491x over previous
#include <cuda_runtime.h>
#include <cstddef>

#define N_NODES   60000
#define N_EDGES   240000
#define WIDTH     256
#define DIM_HEAD  32
#define NUM_HEAD  8
#define TILE      32
#define PITCH     260   // floats; 16B-aligned rows

__device__ float g_aggx[(size_t)N_NODES * WIDTH];     // segment_sum(x[i0])
__device__ float g_t2  [(size_t)N_NODES * DIM_HEAD];  // segment_sum(t2)
__device__ int   g_indeg[N_NODES];
__device__ float g_xld [(size_t)N_NODES * DIM_HEAD];  // x @ lora_down
__device__ float g_Wg  [WIDTH * WIDTH];               // lin_pre @ gate_lin
__device__ float g_Wv  [WIDTH * WIDTH];               // lin_pre @ value_lin
__device__ float g_Wlg [DIM_HEAD * WIDTH];            // lora_up @ gate_lin
__device__ float g_Wlv [DIM_HEAD * WIDTH];            // lora_up @ value_lin

__device__ __forceinline__ float sp(float x) {
    return fmaxf(x, 0.f) + log1pf(expf(-fabsf(x)));
}

__device__ __forceinline__ float wsum(float v) {
#pragma unroll
    for (int o = 16; o; o >>= 1) v += __shfl_xor_sync(0xffffffffu, v, o);
    return v;
}

__device__ __forceinline__ void red_add_v4(float* p, float4 v) {
    asm volatile("red.global.add.v4.f32 [%0], {%1, %2, %3, %4};"
                 :: "l"(p), "f"(v.x), "f"(v.y), "f"(v.z), "f"(v.w)
                 : "memory");
}

// ============================================================================
// Zero scratch
// ============================================================================
__global__ void zero_kernel() {
    size_t n4 = (size_t)N_NODES * WIDTH / 4;
    float4* p = (float4*)g_aggx;
    for (size_t i = (size_t)blockIdx.x * blockDim.x + threadIdx.x; i < n4;
         i += (size_t)gridDim.x * blockDim.x)
        p[i] = make_float4(0.f, 0.f, 0.f, 0.f);
    size_t m4 = (size_t)N_NODES * DIM_HEAD / 4;
    float4* q = (float4*)g_t2;
    for (size_t i = (size_t)blockIdx.x * blockDim.x + threadIdx.x; i < m4;
         i += (size_t)gridDim.x * blockDim.x)
        q[i] = make_float4(0.f, 0.f, 0.f, 0.f);
    for (size_t i = (size_t)blockIdx.x * blockDim.x + threadIdx.x; i < N_NODES;
         i += (size_t)gridDim.x * blockDim.x)
        g_indeg[i] = 0;
}

// ============================================================================
// Precompute combined weight matrices
//   blocks [0,256):   Wg[row]  = lin_pre[row] @ gate_lin
//   blocks [256,512): Wv[row]  = lin_pre[row] @ value_lin
//   blocks [512,544): Wlg[row] = lora_up[row] @ gate_lin
//   blocks [544,576): Wlv[row] = lora_up[row] @ value_lin
// ============================================================================
__global__ __launch_bounds__(256) void wprep_kernel(
    const float* __restrict__ lin_pre,
    const float* __restrict__ lora_up,
    const float* __restrict__ gate_lin,
    const float* __restrict__ value_lin)
{
    int b = blockIdx.x, f = threadIdx.x;
    const float *src, *mult;
    float* dst;
    int row;
    if (b < 256)      { row = b;       src = lin_pre; mult = gate_lin;  dst = g_Wg;  }
    else if (b < 512) { row = b - 256; src = lin_pre; mult = value_lin; dst = g_Wv;  }
    else if (b < 544) { row = b - 512; src = lora_up; mult = gate_lin;  dst = g_Wlg; }
    else              { row = b - 544; src = lora_up; mult = value_lin; dst = g_Wlv; }
    float acc = 0.f;
#pragma unroll 4
    for (int j = 0; j < WIDTH; j++)
        acc += __ldg(&src[row * WIDTH + j]) * __ldg(&mult[j * WIDTH + f]);
    dst[row * WIDTH + f] = acc;
}

// ============================================================================
// Precompute xld = x @ lora_down   [N, 32]
// ============================================================================
__global__ __launch_bounds__(256) void xld_kernel(
    const float* __restrict__ x,
    const float* __restrict__ lora_down)
{
    __shared__ float xs[TILE][PITCH];
    const int tid = threadIdx.x;
    const int nb  = blockIdx.x * TILE;
    {
        const int n  = tid >> 3;
        const int c0 = (tid & 7) * 4;
        const float4* r = (const float4*)(x + (size_t)(nb + n) * WIDTH);
#pragma unroll
        for (int it = 0; it < 8; it++) {
            int c = c0 + it * 32;
            *(float4*)&xs[n][c] = __ldg(&r[c >> 2]);
        }
    }
    __syncthreads();
    const int n = tid >> 3;
    const int d = (tid & 7) * 4;
    float4 acc = make_float4(0.f, 0.f, 0.f, 0.f);
#pragma unroll 4
    for (int k = 0; k < WIDTH; k++) {
        float  m  = xs[n][k];
        float4 ld = __ldg((const float4*)(lora_down + k * 32 + d));
        acc.x += m * ld.x; acc.y += m * ld.y;
        acc.z += m * ld.z; acc.w += m * ld.w;
    }
    *(float4*)&g_xld[(size_t)(nb + n) * 32 + d] = acc;
}

// ============================================================================
// Edge kernel: 32 edges per block
//   emb = sum(emb_edge[attr]) + moa(diff)@elec_lin
//   t2  = (xld[i0]+xld[i1])*emb   -> red into g_t2[i1]
//   x[i0]                         -> red into g_aggx[i1];  g_indeg[i1]++
// ============================================================================
__global__ __launch_bounds__(256) void edge_kernel(
    const float* __restrict__ x,
    const int*   __restrict__ edge_idx,
    const int*   __restrict__ edge_attr,
    const float* __restrict__ node_elec,
    const float* __restrict__ emb_edge,
    const float* __restrict__ moa_w,
    const float* __restrict__ moa_s,
    const float* __restrict__ elec_lin)
{
    __shared__ int   s_i0[TILE], s_i1[TILE];
    __shared__ float emb_s[TILE][33];

    const int tid = threadIdx.x;
    const int eb  = blockIdx.x * TILE;

    if (tid < TILE) {
        int i0 = edge_idx[eb + tid];
        int i1 = edge_idx[N_EDGES + eb + tid];
        s_i0[tid] = i0;
        s_i1[tid] = i1;
        atomicAdd(&g_indeg[i1], 1);
    }
    __syncthreads();

    // --- edge embedding: 4 edges per warp, lane = dim ---
    {
        const int wid = tid >> 5, lane = tid & 31;
        float w0 = sp(moa_w[lane]);
        float w1 = sp(moa_w[32 + lane]);
        w0 /= wsum(w0);
        w1 /= wsum(w1);
        const float s0  = sp(moa_s[lane]);
        const float s1  = sp(moa_s[32 + lane]);
        const float el0 = elec_lin[lane];
        const float el1 = elec_lin[32 + lane];
#pragma unroll
        for (int i = 0; i < 4; i++) {
            int e  = wid * 4 + i;
            int i0 = s_i0[e], i1 = s_i1[e];
            float d0 = node_elec[2 * i0]     - node_elec[2 * i1];
            float d1 = node_elec[2 * i0 + 1] - node_elec[2 * i1 + 1];
            float m0 = wsum(tanhf(d0 * s0) * w0);
            float m1 = wsum(tanhf(d1 * s1) * w1);
            int ge = eb + e;
            int a0 = edge_attr[3 * ge], a1 = edge_attr[3 * ge + 1], a2 = edge_attr[3 * ge + 2];
            emb_s[e][lane] = emb_edge[a0 * 32 + lane] + emb_edge[a1 * 32 + lane] +
                             emb_edge[a2 * 32 + lane] + m0 * el0 + m1 * el1;
        }
    }
    __syncthreads();

    const int e  = tid >> 3;
    const int i0 = s_i0[e], i1 = s_i1[e];

    // --- t2 scatter (rank-32) ---
    {
        const int d = (tid & 7) * 4;
        float4 a = __ldg((const float4*)(g_xld + (size_t)i0 * 32 + d));
        float4 b = __ldg((const float4*)(g_xld + (size_t)i1 * 32 + d));
        float4 t;
        t.x = (a.x + b.x) * emb_s[e][d + 0];
        t.y = (a.y + b.y) * emb_s[e][d + 1];
        t.z = (a.z + b.z) * emb_s[e][d + 2];
        t.w = (a.w + b.w) * emb_s[e][d + 3];
        red_add_v4(g_t2 + (size_t)i1 * 32 + d, t);
    }

    // --- x[i0] scatter into g_aggx[i1] ---
    {
        const int c0 = (tid & 7) * 4;
        const float4* xr = (const float4*)(x + (size_t)i0 * WIDTH);
        float* dst = g_aggx + (size_t)i1 * WIDTH;
#pragma unroll
        for (int it = 0; it < 8; it++) {
            int c = c0 + it * 32;
            float4 v = __ldg(&xr[c >> 2]);
            red_add_v4(dst + c, v);
        }
    }
}

// ============================================================================
// Node kernel: per 32-node tile
//   raw = g_aggx[n] + indeg[n]*x[n]
//   U = raw@Wg + t2@Wlg ; V = raw@Wv + t2@Wlv
//   per-head RMS norm (+deg bias on gate), head GEMMs, softplus gate, post GEMM
// ============================================================================
__global__ __launch_bounds__(256) void node_kernel(
    const float* __restrict__ x,
    const int*   __restrict__ deg,
    const float* __restrict__ emb_deg,
    const float* __restrict__ gate_kernel,
    const float* __restrict__ value_kernel,
    const float* __restrict__ act_bias,
    const float* __restrict__ post_kernel,
    float*       __restrict__ out)
{
    extern __shared__ float sm[];
    float* staged = sm;                     // [32][PITCH] raw agg; later avv (pitch 132)
    float* u_s    = sm + 32 * PITCH;        // [32][PITCH]
    float* v_s    = sm + 2 * 32 * PITCH;    // [32][PITCH]
    float* t2_s   = sm + 3 * 32 * PITCH;    // [32][36]
    float* avv_s  = staged;

    const int tid = threadIdx.x;
    const int nb  = blockIdx.x * TILE;

    // --- load raw agg + t2 tiles ---
    {
        const int n  = tid >> 3;
        const int gn = nb + n;
        const int c0 = (tid & 7) * 4;
        const float idg = (float)__ldg(&g_indeg[gn]);
        const float4* ra = (const float4*)(g_aggx + (size_t)gn * WIDTH);
        const float4* rx = (const float4*)(x + (size_t)gn * WIDTH);
#pragma unroll
        for (int it = 0; it < 8; it++) {
            int c = c0 + it * 32;
            float4 a  = ra[c >> 2];
            float4 xv = __ldg(&rx[c >> 2]);
            *(float4*)&staged[n * PITCH + c] =
                make_float4(a.x + idg * xv.x, a.y + idg * xv.y,
                            a.z + idg * xv.z, a.w + idg * xv.w);
        }
        const int d = (tid & 7) * 4;
        *(float4*)&t2_s[n * 36 + d] =
            *(const float4*)(g_t2 + (size_t)gn * 32 + d);
    }
    __syncthreads();

    // --- U and V: [32,288] @ [288,256] split as raw@W + t2@Wl ---
    {
        const int f  = (tid & 63) * 4;
        const int n0 = (tid >> 6) * 8;
#pragma unroll 1
        for (int pass = 0; pass < 2; pass++) {
            const float* W  = pass ? g_Wv  : g_Wg;
            const float* Wl = pass ? g_Wlv : g_Wlg;
            float* Odst     = pass ? v_s   : u_s;
            float4 acc[8];
#pragma unroll
            for (int j = 0; j < 8; j++) acc[j] = make_float4(0.f, 0.f, 0.f, 0.f);
#pragma unroll 2
            for (int k = 0; k < WIDTH; k++) {
                float4 w4 = __ldg((const float4*)(W + k * WIDTH + f));
#pragma unroll
                for (int j = 0; j < 8; j++) {
                    float m = staged[(n0 + j) * PITCH + k];
                    acc[j].x += m * w4.x; acc[j].y += m * w4.y;
                    acc[j].z += m * w4.z; acc[j].w += m * w4.w;
                }
            }
#pragma unroll 2
            for (int d = 0; d < DIM_HEAD; d++) {
                float4 u4 = __ldg((const float4*)(Wl + d * WIDTH + f));
#pragma unroll
                for (int j = 0; j < 8; j++) {
                    float m = t2_s[(n0 + j) * 36 + d];
                    acc[j].x += m * u4.x; acc[j].y += m * u4.y;
                    acc[j].z += m * u4.z; acc[j].w += m * u4.w;
                }
            }
#pragma unroll
            for (int j = 0; j < 8; j++)
                *(float4*)&Odst[(n0 + j) * PITCH + f] = acc[j];
        }
    }
    __syncthreads();

    // --- per-(node,head) RMS norm; gate adds deg-bias and /sqrt(2) ---
    {
        const int n = tid & 31, h = tid >> 5;
        const int gn = nb + n;
        const int dd = __ldg(&deg[gn]);
        const float inv_s2 = 0.70710678118654752440f;

        float4 uu[8];
        float ss = 0.f;
#pragma unroll
        for (int i = 0; i < 8; i++) {
            uu[i] = *(float4*)&u_s[n * PITCH + h * 32 + 4 * i];
            ss += uu[i].x * uu[i].x + uu[i].y * uu[i].y +
                  uu[i].z * uu[i].z + uu[i].w * uu[i].w;
        }
        float rinv = rsqrtf(ss * (1.f / 32.f) + 1e-6f);
#pragma unroll
        for (int i = 0; i < 8; i++) {
            float4 b = __ldg((const float4*)(emb_deg + dd * 256 + h * 32 + 4 * i));
            float4 o;
            o.x = (uu[i].x * rinv + b.x) * inv_s2;
            o.y = (uu[i].y * rinv + b.y) * inv_s2;
            o.z = (uu[i].z * rinv + b.z) * inv_s2;
            o.w = (uu[i].w * rinv + b.w) * inv_s2;
            *(float4*)&u_s[n * PITCH + h * 32 + 4 * i] = o;
        }

        float4 vv4[8];
        float ssv = 0.f;
#pragma unroll
        for (int i = 0; i < 8; i++) {
            vv4[i] = *(float4*)&v_s[n * PITCH + h * 32 + 4 * i];
            ssv += vv4[i].x * vv4[i].x + vv4[i].y * vv4[i].y +
                   vv4[i].z * vv4[i].z + vv4[i].w * vv4[i].w;
        }
        float rinvv = rsqrtf(ssv * (1.f / 32.f) + 1e-6f);
#pragma unroll
        for (int i = 0; i < 8; i++) {
            float4 o;
            o.x = vv4[i].x * rinvv; o.y = vv4[i].y * rinvv;
            o.z = vv4[i].z * rinvv; o.w = vv4[i].w * rinvv;
            *(float4*)&v_s[n * PITCH + h * 32 + 4 * i] = o;
        }
    }
    __syncthreads();

    const float CLIP_LO = 0.22360679774997896f;   // 1/sqrt(20)
    const float CLIP_HI = 4.47213595499957939f;   // sqrt(20)

    // --- per-head gate/value GEMMs + activation + post GEMM ---
#pragma unroll 1
    for (int h = 0; h < NUM_HEAD; h++) {
        {
            const int f2 = (tid & 31) * 4;
            const int n0 = (tid >> 5) * 4;
            const float* GK = gate_kernel  + h * 32 * 128;
            const float* VK = value_kernel + h * 32 * 128;
            float4 ag[4], av[4];
#pragma unroll
            for (int j = 0; j < 4; j++) {
                ag[j] = make_float4(0.f, 0.f, 0.f, 0.f);
                av[j] = make_float4(0.f, 0.f, 0.f, 0.f);
            }
#pragma unroll 2
            for (int d = 0; d < 32; d++) {
                float4 g4 = __ldg((const float4*)(GK + d * 128 + f2));
                float4 v4 = __ldg((const float4*)(VK + d * 128 + f2));
#pragma unroll
                for (int j = 0; j < 4; j++) {
                    float ub = u_s[(n0 + j) * PITCH + h * 32 + d];
                    float vb = v_s[(n0 + j) * PITCH + h * 32 + d];
                    ag[j].x += ub * g4.x; ag[j].y += ub * g4.y;
                    ag[j].z += ub * g4.z; ag[j].w += ub * g4.w;
                    av[j].x += vb * v4.x; av[j].y += vb * v4.y;
                    av[j].z += vb * v4.z; av[j].w += vb * v4.w;
                }
            }
            float4 ab = __ldg((const float4*)(act_bias + h * 128 + f2));
#pragma unroll
            for (int j = 0; j < 4; j++) {
                float4 o;
                o.x = fminf(fmaxf(sp(ag[j].x + ab.x), CLIP_LO), CLIP_HI) * av[j].x;
                o.y = fminf(fmaxf(sp(ag[j].y + ab.y), CLIP_LO), CLIP_HI) * av[j].y;
                o.z = fminf(fmaxf(sp(ag[j].z + ab.z), CLIP_LO), CLIP_HI) * av[j].z;
                o.w = fminf(fmaxf(sp(ag[j].w + ab.w), CLIP_LO), CLIP_HI) * av[j].w;
                *(float4*)&avv_s[(n0 + j) * 132 + f2] = o;
            }
        }
        __syncthreads();
        {
            const int d2 = (tid & 7) * 4;
            const int n  = tid >> 3;
            const float* PK = post_kernel + h * 128 * 32;
            float4 acc = make_float4(0.f, 0.f, 0.f, 0.f);
#pragma unroll 4
            for (int f2 = 0; f2 < 128; f2++) {
                float4 p4 = __ldg((const float4*)(PK + f2 * 32 + d2));
                float  a  = avv_s[n * 132 + f2];
                acc.x += a * p4.x; acc.y += a * p4.y;
                acc.z += a * p4.z; acc.w += a * p4.w;
            }
            *(float4*)&out[(size_t)(nb + n) * WIDTH + h * 32 + d2] = acc;
        }
        __syncthreads();
    }
}

// ============================================================================
// Launch
// ============================================================================
extern "C" void kernel_launch(void* const* d_in, const int* in_sizes, int n_in,
                              void* d_out, int out_size) {
    const float* x            = (const float*)d_in[0];
    const int*   deg          = (const int*)  d_in[1];
    const int*   edge_idx     = (const int*)  d_in[2];
    const int*   edge_attr    = (const int*)  d_in[3];
    const float* node_elec    = (const float*)d_in[4];
    const float* lora_down    = (const float*)d_in[5];
    const float* lora_up      = (const float*)d_in[6];
    const float* emb_edge     = (const float*)d_in[7];
    const float* moa_w        = (const float*)d_in[8];
    const float* moa_s        = (const float*)d_in[9];
    const float* elec_lin     = (const float*)d_in[10];
    const float* emb_deg      = (const float*)d_in[11];
    const float* lin_pre      = (const float*)d_in[12];
    const float* gate_lin     = (const float*)d_in[13];
    const float* gate_kernel  = (const float*)d_in[14];
    const float* value_lin    = (const float*)d_in[15];
    const float* value_kernel = (const float*)d_in[16];
    const float* act_bias     = (const float*)d_in[17];
    const float* post_kernel  = (const float*)d_in[18];
    float* out = (float*)d_out;

    zero_kernel<<<2048, 256>>>();
    wprep_kernel<<<576, 256>>>(lin_pre, lora_up, gate_lin, value_lin);
    xld_kernel<<<N_NODES / TILE, 256>>>(x, lora_down);
    edge_kernel<<<N_EDGES / TILE, 256>>>(
        x, edge_idx, edge_attr, node_elec,
        emb_edge, moa_w, moa_s, elec_lin);

    size_t nsm = ((size_t)3 * 32 * PITCH + 32 * 36) * sizeof(float);  // 104448 B
    cudaFuncSetAttribute(node_kernel,
                         cudaFuncAttributeMaxDynamicSharedMemorySize, (int)nsm);
    node_kernel<<<N_NODES / TILE, 256, nsm>>>(
        x, deg, emb_deg, gate_kernel, value_kernel,
        act_bias, post_kernel, out);
}

// round 5
// speedup vs baseline: 4.5088x; 3.1114x over previous
#include <cuda_runtime.h>
#include <cstddef>

#define N_NODES   60000
#define N_EDGES   240000
#define WIDTH     256
#define DIM_HEAD  32
#define NUM_HEAD  8
#define TILE      32

// ---------------------------------------------------------------------------
// Device scratch
// ---------------------------------------------------------------------------
__device__ float g_aggx[(size_t)N_NODES * WIDTH];     // segment_sum(x[i0])
__device__ float g_t2  [(size_t)N_NODES * DIM_HEAD];  // segment_sum(t2)
__device__ int   g_indeg[N_NODES];
__device__ float g_xld [(size_t)N_NODES * DIM_HEAD];  // x @ lora_down

// mma-fragment-swizzled weights (tf32-rounded fp32 bit patterns)
__device__ float g_W2f[36 * 4 * 16 * 32 * 2];  // [ks][wn][nt][lane][2] of W2 288x512
__device__ float g_GVf[2 * 8 * 4 * 16 * 32 * 2];
__device__ float g_Pf [8 * 16 * 4 * 32 * 2];

__device__ __forceinline__ float sp(float x) {
    return fmaxf(x, 0.f) + log1pf(expf(-fabsf(x)));
}
__device__ __forceinline__ float wsum(float v) {
#pragma unroll
    for (int o = 16; o; o >>= 1) v += __shfl_xor_sync(0xffffffffu, v, o);
    return v;
}
__device__ __forceinline__ void red_add_v4(float* p, float4 v) {
    asm volatile("red.global.add.v4.f32 [%0], {%1, %2, %3, %4};"
                 :: "l"(p), "f"(v.x), "f"(v.y), "f"(v.z), "f"(v.w)
                 : "memory");
}
__device__ __forceinline__ unsigned f2tf(float f) {
    unsigned r;
    asm("cvt.rna.tf32.f32 %0, %1;" : "=r"(r) : "f"(f));
    return r;
}
__device__ __forceinline__ float tf32r(float f) {
    return __uint_as_float(f2tf(f));
}
__device__ __forceinline__ void mma_tf32(float4& c,
    unsigned a0, unsigned a1, unsigned a2, unsigned a3,
    unsigned b0, unsigned b1)
{
    asm volatile(
        "mma.sync.aligned.m16n8k8.row.col.f32.tf32.tf32.f32 "
        "{%0,%1,%2,%3},{%4,%5,%6,%7},{%8,%9},{%0,%1,%2,%3};"
        : "+f"(c.x), "+f"(c.y), "+f"(c.z), "+f"(c.w)
        : "r"(a0), "r"(a1), "r"(a2), "r"(a3), "r"(b0), "r"(b1));
}

// ---------------------------------------------------------------------------
// Zero scratch
// ---------------------------------------------------------------------------
__global__ void zero_kernel() {
    size_t n4 = (size_t)N_NODES * WIDTH / 4;
    float4* p = (float4*)g_aggx;
    for (size_t i = (size_t)blockIdx.x * blockDim.x + threadIdx.x; i < n4;
         i += (size_t)gridDim.x * blockDim.x)
        p[i] = make_float4(0.f, 0.f, 0.f, 0.f);
    size_t m4 = (size_t)N_NODES * DIM_HEAD / 4;
    float4* q = (float4*)g_t2;
    for (size_t i = (size_t)blockIdx.x * blockDim.x + threadIdx.x; i < m4;
         i += (size_t)gridDim.x * blockDim.x)
        q[i] = make_float4(0.f, 0.f, 0.f, 0.f);
    for (size_t i = (size_t)blockIdx.x * blockDim.x + threadIdx.x; i < N_NODES;
         i += (size_t)gridDim.x * blockDim.x)
        g_indeg[i] = 0;
}

// ---------------------------------------------------------------------------
// W2 = [lin_pre; lora_up] @ [gate_lin | value_lin], stored mma-B swizzled.
// thread per (k,n): k in [0,288), n in [0,512)
// ---------------------------------------------------------------------------
__global__ __launch_bounds__(256) void wprep_w2_kernel(
    const float* __restrict__ lin_pre,
    const float* __restrict__ lora_up,
    const float* __restrict__ gate_lin,
    const float* __restrict__ value_lin)
{
    int id = blockIdx.x * 256 + threadIdx.x;   // 576 blocks -> 147456
    int k = id >> 9;
    int n = id & 511;
    const float* srow = (k < 256) ? (lin_pre + k * 256) : (lora_up + (k - 256) * 256);
    const float* M    = (n < 256) ? gate_lin : value_lin;
    int nn = n & 255;
    float acc = 0.f;
#pragma unroll 4
    for (int j = 0; j < 256; j++)
        acc += __ldg(&srow[j]) * __ldg(&M[j * 256 + nn]);
    int ks = k >> 3, kin = k & 7, tig = kin & 3, jj = kin >> 2;
    int wn = n >> 7, rem = n & 127, nt = rem >> 3, g = rem & 7;
    int idx = ((((ks * 4 + wn) * 16 + nt) * 32) + (g * 4 + tig)) * 2 + jj;
    g_W2f[idx] = tf32r(acc);
}

// ---------------------------------------------------------------------------
// Swizzle gate_kernel / value_kernel / post_kernel into mma-B fragment order.
// ---------------------------------------------------------------------------
__global__ __launch_bounds__(256) void wprep_swz_kernel(
    const float* __restrict__ gate_kernel,
    const float* __restrict__ value_kernel,
    const float* __restrict__ post_kernel)
{
    int id = blockIdx.x * 256 + threadIdx.x;   // 384 blocks -> 98304
    if (id < 65536) {
        int path = id >> 15;
        int rem  = id & 32767;
        int h    = rem >> 12;
        int rem2 = rem & 4095;
        int d    = rem2 >> 7;
        int f    = rem2 & 127;
        float val = path ? __ldg(&value_kernel[h * 4096 + d * 128 + f])
                         : __ldg(&gate_kernel [h * 4096 + d * 128 + f]);
        int ks = d >> 3, kin = d & 7, tig = kin & 3, jj = kin >> 2;
        int nt = f >> 3, g = f & 7;
        int idx = (((((path * 8 + h) * 4 + ks) * 16 + nt) * 32) + (g * 4 + tig)) * 2 + jj;
        g_GVf[idx] = tf32r(val);
    } else {
        int p = id - 65536;
        int h = p >> 12;
        int rem = p & 4095;
        int f = rem >> 5;
        int d2 = rem & 31;
        float val = __ldg(&post_kernel[h * 4096 + f * 32 + d2]);
        int ks = f >> 3, kin = f & 7, tig = kin & 3, jj = kin >> 2;
        int nt = d2 >> 3, g = d2 & 7;
        int idx = ((((h * 16 + ks) * 4 + nt) * 32) + (g * 4 + tig)) * 2 + jj;
        g_Pf[idx] = tf32r(val);
    }
}

// ---------------------------------------------------------------------------
// xld = x @ lora_down   [N, 32]
// ---------------------------------------------------------------------------
__global__ __launch_bounds__(256) void xld_kernel(
    const float* __restrict__ x,
    const float* __restrict__ lora_down)
{
    __shared__ float xs[TILE][260];
    const int tid = threadIdx.x;
    const int nb  = blockIdx.x * TILE;
    {
        const int n  = tid >> 3;
        const int c0 = (tid & 7) * 4;
        const float4* r = (const float4*)(x + (size_t)(nb + n) * WIDTH);
#pragma unroll
        for (int it = 0; it < 8; it++) {
            int c = c0 + it * 32;
            *(float4*)&xs[n][c] = __ldg(&r[c >> 2]);
        }
    }
    __syncthreads();
    const int n = tid >> 3;
    const int d = (tid & 7) * 4;
    float4 acc = make_float4(0.f, 0.f, 0.f, 0.f);
#pragma unroll 4
    for (int k = 0; k < WIDTH; k++) {
        float  m  = xs[n][k];
        float4 ld = __ldg((const float4*)(lora_down + k * 32 + d));
        acc.x += m * ld.x; acc.y += m * ld.y;
        acc.z += m * ld.z; acc.w += m * ld.w;
    }
    *(float4*)&g_xld[(size_t)(nb + n) * 32 + d] = acc;
}

// ---------------------------------------------------------------------------
// Edge kernel (unchanged from round 4)
// ---------------------------------------------------------------------------
__global__ __launch_bounds__(256) void edge_kernel(
    const float* __restrict__ x,
    const int*   __restrict__ edge_idx,
    const int*   __restrict__ edge_attr,
    const float* __restrict__ node_elec,
    const float* __restrict__ emb_edge,
    const float* __restrict__ moa_w,
    const float* __restrict__ moa_s,
    const float* __restrict__ elec_lin)
{
    __shared__ int   s_i0[TILE], s_i1[TILE];
    __shared__ float emb_s[TILE][33];

    const int tid = threadIdx.x;
    const int eb  = blockIdx.x * TILE;

    if (tid < TILE) {
        int i0 = edge_idx[eb + tid];
        int i1 = edge_idx[N_EDGES + eb + tid];
        s_i0[tid] = i0;
        s_i1[tid] = i1;
        atomicAdd(&g_indeg[i1], 1);
    }
    __syncthreads();

    {
        const int wid = tid >> 5, lane = tid & 31;
        float w0 = sp(moa_w[lane]);
        float w1 = sp(moa_w[32 + lane]);
        w0 /= wsum(w0);
        w1 /= wsum(w1);
        const float s0  = sp(moa_s[lane]);
        const float s1  = sp(moa_s[32 + lane]);
        const float el0 = elec_lin[lane];
        const float el1 = elec_lin[32 + lane];
#pragma unroll
        for (int i = 0; i < 4; i++) {
            int e  = wid * 4 + i;
            int i0 = s_i0[e], i1 = s_i1[e];
            float d0 = node_elec[2 * i0]     - node_elec[2 * i1];
            float d1 = node_elec[2 * i0 + 1] - node_elec[2 * i1 + 1];
            float m0 = wsum(tanhf(d0 * s0) * w0);
            float m1 = wsum(tanhf(d1 * s1) * w1);
            int ge = eb + e;
            int a0 = edge_attr[3 * ge], a1 = edge_attr[3 * ge + 1], a2 = edge_attr[3 * ge + 2];
            emb_s[e][lane] = emb_edge[a0 * 32 + lane] + emb_edge[a1 * 32 + lane] +
                             emb_edge[a2 * 32 + lane] + m0 * el0 + m1 * el1;
        }
    }
    __syncthreads();

    const int e  = tid >> 3;
    const int i0 = s_i0[e], i1 = s_i1[e];

    {
        const int d = (tid & 7) * 4;
        float4 a = __ldg((const float4*)(g_xld + (size_t)i0 * 32 + d));
        float4 b = __ldg((const float4*)(g_xld + (size_t)i1 * 32 + d));
        float4 t;
        t.x = (a.x + b.x) * emb_s[e][d + 0];
        t.y = (a.y + b.y) * emb_s[e][d + 1];
        t.z = (a.z + b.z) * emb_s[e][d + 2];
        t.w = (a.w + b.w) * emb_s[e][d + 3];
        red_add_v4(g_t2 + (size_t)i1 * 32 + d, t);
    }
    {
        const int c0 = (tid & 7) * 4;
        const float4* xr = (const float4*)(x + (size_t)i0 * WIDTH);
        float* dst = g_aggx + (size_t)i1 * WIDTH;
#pragma unroll
        for (int it = 0; it < 8; it++) {
            int c = c0 + it * 32;
            float4 v = __ldg(&xr[c >> 2]);
            red_add_v4(dst + c, v);
        }
    }
}

// ---------------------------------------------------------------------------
// Node kernel: all four GEMM stages on mma.tf32
// smem: A_s[32][292] (raw|t2, tf32) ; u_s[32][260] ; v_s[32][260]
//       avv_s reuses A_s with pitch 132
// ---------------------------------------------------------------------------
__global__ __launch_bounds__(256) void node_kernel(
    const float* __restrict__ x,
    const int*   __restrict__ deg,
    const float* __restrict__ emb_deg,
    const float* __restrict__ act_bias,
    float*       __restrict__ out)
{
    extern __shared__ float sm[];
    float* A_s  = sm;                    // [32][292]
    float* u_s  = sm + 32 * 292;         // [32][260]
    float* v_s  = u_s + 32 * 260;        // [32][260]
    float* avv_s = A_s;                  // [32][132] (reuse)

    const int tid  = threadIdx.x;
    const int nb   = blockIdx.x * TILE;
    const int lane = tid & 31, wid = tid >> 5;
    const int g = lane >> 2, t = lane & 3;
    const int wm = wid >> 2, wn = wid & 3;
    const int m0 = wm * 16;

    // --- stage inputs (tf32-rounded) ---
    {
        const int n  = tid >> 3;
        const int gn = nb + n;
        const int c0 = (tid & 7) * 4;
        const float idg = (float)__ldg(&g_indeg[gn]);
        const float4* ra = (const float4*)(g_aggx + (size_t)gn * WIDTH);
        const float4* rx = (const float4*)(x + (size_t)gn * WIDTH);
#pragma unroll
        for (int it = 0; it < 8; it++) {
            int c = c0 + it * 32;
            float4 a  = ra[c >> 2];
            float4 xv = __ldg(&rx[c >> 2]);
            A_s[n * 292 + c + 0] = tf32r(a.x + idg * xv.x);
            A_s[n * 292 + c + 1] = tf32r(a.y + idg * xv.y);
            A_s[n * 292 + c + 2] = tf32r(a.z + idg * xv.z);
            A_s[n * 292 + c + 3] = tf32r(a.w + idg * xv.w);
        }
        const int d = (tid & 7) * 4;
        float4 t2v = *(const float4*)(g_t2 + (size_t)gn * 32 + d);
        A_s[n * 292 + 256 + d + 0] = tf32r(t2v.x);
        A_s[n * 292 + 256 + d + 1] = tf32r(t2v.y);
        A_s[n * 292 + 256 + d + 2] = tf32r(t2v.z);
        A_s[n * 292 + 256 + d + 3] = tf32r(t2v.w);
    }
    __syncthreads();

    // --- Stage A: [32x288] @ W2[288x512] -> U|V ---
    {
        const unsigned* Au = (const unsigned*)A_s;
        const int r0 = (m0 + g) * 292;
        const int r1 = r0 + 8 * 292;
        float4 acc[16];
#pragma unroll
        for (int i = 0; i < 16; i++) acc[i] = make_float4(0.f, 0.f, 0.f, 0.f);

#pragma unroll 4
        for (int ks = 0; ks < 36; ks++) {
            int kc = ks * 8 + t;
            unsigned a0 = Au[r0 + kc];
            unsigned a1 = Au[r1 + kc];
            unsigned a2 = Au[r0 + kc + 4];
            unsigned a3 = Au[r1 + kc + 4];
            const uint2* Bp = ((const uint2*)g_W2f) + ((ks * 4 + wn) * 16) * 32 + lane;
#pragma unroll
            for (int nt = 0; nt < 16; nt++) {
                uint2 b = __ldg(&Bp[nt * 32]);
                mma_tf32(acc[nt], a0, a1, a2, a3, b.x, b.y);
            }
        }
        float* dst = (wn < 2) ? u_s : v_s;
        const int nb0 = (wn & 1) * 128;
#pragma unroll
        for (int nt = 0; nt < 16; nt++) {
            int c = nb0 + nt * 8 + 2 * t;
            *(float2*)&dst[(m0 + g)     * 260 + c] = make_float2(acc[nt].x, acc[nt].y);
            *(float2*)&dst[(m0 + g + 8) * 260 + c] = make_float2(acc[nt].z, acc[nt].w);
        }
    }
    __syncthreads();

    // --- per-(node,head) RMS norm; gate adds deg-bias, /sqrt2; tf32-round ---
    {
        const int n = tid & 31, h = tid >> 5;
        const int gn = nb + n;
        const int dd = __ldg(&deg[gn]);
        const float inv_s2 = 0.70710678118654752440f;

        float4 uu[8];
        float ss = 0.f;
#pragma unroll
        for (int i = 0; i < 8; i++) {
            uu[i] = *(float4*)&u_s[n * 260 + h * 32 + 4 * i];
            ss += uu[i].x * uu[i].x + uu[i].y * uu[i].y +
                  uu[i].z * uu[i].z + uu[i].w * uu[i].w;
        }
        float rinv = rsqrtf(ss * (1.f / 32.f) + 1e-6f);
#pragma unroll
        for (int i = 0; i < 8; i++) {
            float4 b = __ldg((const float4*)(emb_deg + dd * 256 + h * 32 + 4 * i));
            u_s[n * 260 + h * 32 + 4 * i + 0] = tf32r((uu[i].x * rinv + b.x) * inv_s2);
            u_s[n * 260 + h * 32 + 4 * i + 1] = tf32r((uu[i].y * rinv + b.y) * inv_s2);
            u_s[n * 260 + h * 32 + 4 * i + 2] = tf32r((uu[i].z * rinv + b.z) * inv_s2);
            u_s[n * 260 + h * 32 + 4 * i + 3] = tf32r((uu[i].w * rinv + b.w) * inv_s2);
        }
        float4 vv4[8];
        float ssv = 0.f;
#pragma unroll
        for (int i = 0; i < 8; i++) {
            vv4[i] = *(float4*)&v_s[n * 260 + h * 32 + 4 * i];
            ssv += vv4[i].x * vv4[i].x + vv4[i].y * vv4[i].y +
                   vv4[i].z * vv4[i].z + vv4[i].w * vv4[i].w;
        }
        float rinvv = rsqrtf(ssv * (1.f / 32.f) + 1e-6f);
#pragma unroll
        for (int i = 0; i < 8; i++) {
            v_s[n * 260 + h * 32 + 4 * i + 0] = tf32r(vv4[i].x * rinvv);
            v_s[n * 260 + h * 32 + 4 * i + 1] = tf32r(vv4[i].y * rinvv);
            v_s[n * 260 + h * 32 + 4 * i + 2] = tf32r(vv4[i].z * rinvv);
            v_s[n * 260 + h * 32 + 4 * i + 3] = tf32r(vv4[i].w * rinvv);
        }
    }
    __syncthreads();

    const float CLIP_LO = 0.22360679774997896f;
    const float CLIP_HI = 4.47213595499957939f;
    const unsigned* U32 = (const unsigned*)u_s;
    const unsigned* V32 = (const unsigned*)v_s;
    const unsigned* AV32 = (const unsigned*)avv_s;

#pragma unroll 1
    for (int h = 0; h < NUM_HEAD; h++) {
        // --- Stage B: gate & value head GEMMs [32x32]@[32x128] ---
        {
            const int n0 = wn * 32;
            float4 ag[4], av[4];
#pragma unroll
            for (int i = 0; i < 4; i++) {
                ag[i] = make_float4(0.f, 0.f, 0.f, 0.f);
                av[i] = make_float4(0.f, 0.f, 0.f, 0.f);
            }
#pragma unroll
            for (int ks = 0; ks < 4; ks++) {
                int col = h * 32 + ks * 8 + t;
                unsigned ua0 = U32[(m0 + g)     * 260 + col];
                unsigned ua1 = U32[(m0 + g + 8) * 260 + col];
                unsigned ua2 = U32[(m0 + g)     * 260 + col + 4];
                unsigned ua3 = U32[(m0 + g + 8) * 260 + col + 4];
                unsigned va0 = V32[(m0 + g)     * 260 + col];
                unsigned va1 = V32[(m0 + g + 8) * 260 + col];
                unsigned va2 = V32[(m0 + g)     * 260 + col + 4];
                unsigned va3 = V32[(m0 + g + 8) * 260 + col + 4];
                const uint2* Bg = ((const uint2*)g_GVf) +
                    (((h      * 4 + ks) * 16 + wn * 4) * 32) + lane;
                const uint2* Bv = ((const uint2*)g_GVf) +
                    ((((8 + h) * 4 + ks) * 16 + wn * 4) * 32) + lane;
#pragma unroll
                for (int nt = 0; nt < 4; nt++) {
                    uint2 bg = __ldg(&Bg[nt * 32]);
                    mma_tf32(ag[nt], ua0, ua1, ua2, ua3, bg.x, bg.y);
                    uint2 bv = __ldg(&Bv[nt * 32]);
                    mma_tf32(av[nt], va0, va1, va2, va3, bv.x, bv.y);
                }
            }
#pragma unroll
            for (int nt = 0; nt < 4; nt++) {
                int c = n0 + nt * 8 + 2 * t;
                float2 bias = __ldg((const float2*)(act_bias + h * 128 + c));
                float o0 = fminf(fmaxf(sp(ag[nt].x + bias.x), CLIP_LO), CLIP_HI) * av[nt].x;
                float o1 = fminf(fmaxf(sp(ag[nt].y + bias.y), CLIP_LO), CLIP_HI) * av[nt].y;
                float o2 = fminf(fmaxf(sp(ag[nt].z + bias.x), CLIP_LO), CLIP_HI) * av[nt].z;
                float o3 = fminf(fmaxf(sp(ag[nt].w + bias.y), CLIP_LO), CLIP_HI) * av[nt].w;
                avv_s[(m0 + g)     * 132 + c + 0] = tf32r(o0);
                avv_s[(m0 + g)     * 132 + c + 1] = tf32r(o1);
                avv_s[(m0 + g + 8) * 132 + c + 0] = tf32r(o2);
                avv_s[(m0 + g + 8) * 132 + c + 1] = tf32r(o3);
            }
        }
        __syncthreads();

        // --- Stage D: out_h = avv[32x128] @ post_kernel[h][128x32] ---
        {
            float4 dacc = make_float4(0.f, 0.f, 0.f, 0.f);
#pragma unroll
            for (int ks = 0; ks < 16; ks++) {
                int kc = ks * 8 + t;
                unsigned a0 = AV32[(m0 + g)     * 132 + kc];
                unsigned a1 = AV32[(m0 + g + 8) * 132 + kc];
                unsigned a2 = AV32[(m0 + g)     * 132 + kc + 4];
                unsigned a3 = AV32[(m0 + g + 8) * 132 + kc + 4];
                uint2 b = __ldg(((const uint2*)g_Pf) +
                                (((h * 16 + ks) * 4 + wn) * 32) + lane);
                mma_tf32(dacc, a0, a1, a2, a3, b.x, b.y);
            }
            int col = h * 32 + wn * 8 + 2 * t;
            *(float2*)&out[(size_t)(nb + m0 + g)     * WIDTH + col] =
                make_float2(dacc.x, dacc.y);
            *(float2*)&out[(size_t)(nb + m0 + g + 8) * WIDTH + col] =
                make_float2(dacc.z, dacc.w);
        }
        __syncthreads();
    }
}

// ---------------------------------------------------------------------------
// Launch
// ---------------------------------------------------------------------------
extern "C" void kernel_launch(void* const* d_in, const int* in_sizes, int n_in,
                              void* d_out, int out_size) {
    const float* x            = (const float*)d_in[0];
    const int*   deg          = (const int*)  d_in[1];
    const int*   edge_idx     = (const int*)  d_in[2];
    const int*   edge_attr    = (const int*)  d_in[3];
    const float* node_elec    = (const float*)d_in[4];
    const float* lora_down    = (const float*)d_in[5];
    const float* lora_up      = (const float*)d_in[6];
    const float* emb_edge     = (const float*)d_in[7];
    const float* moa_w        = (const float*)d_in[8];
    const float* moa_s        = (const float*)d_in[9];
    const float* elec_lin     = (const float*)d_in[10];
    const float* emb_deg      = (const float*)d_in[11];
    const float* lin_pre      = (const float*)d_in[12];
    const float* gate_lin     = (const float*)d_in[13];
    const float* gate_kernel  = (const float*)d_in[14];
    const float* value_lin    = (const float*)d_in[15];
    const float* value_kernel = (const float*)d_in[16];
    const float* act_bias     = (const float*)d_in[17];
    const float* post_kernel  = (const float*)d_in[18];
    float* out = (float*)d_out;

    zero_kernel<<<2048, 256>>>();
    wprep_w2_kernel<<<576, 256>>>(lin_pre, lora_up, gate_lin, value_lin);
    wprep_swz_kernel<<<384, 256>>>(gate_kernel, value_kernel, post_kernel);
    xld_kernel<<<N_NODES / TILE, 256>>>(x, lora_down);
    edge_kernel<<<N_EDGES / TILE, 256>>>(
        x, edge_idx, edge_attr, node_elec,
        emb_edge, moa_w, moa_s, elec_lin);

    size_t nsm = ((size_t)32 * 292 + 2 * 32 * 260) * sizeof(float);  // 103936 B
    cudaFuncSetAttribute(node_kernel,
                         cudaFuncAttributeMaxDynamicSharedMemorySize, (int)nsm);
    node_kernel<<<N_NODES / TILE, 256, nsm>>>(
        x, deg, emb_deg, act_bias, out);
}

// round 6
// speedup vs baseline: 4.5983x; 1.0198x over previous
#include <cuda_runtime.h>
#include <cstddef>

#define N_NODES   60000
#define N_EDGES   240000
#define WIDTH     256
#define DIM_HEAD  32
#define NUM_HEAD  8
#define MTILE     64

// ---------------------------------------------------------------------------
// Device scratch
// ---------------------------------------------------------------------------
__device__ float g_aggx[(size_t)N_NODES * WIDTH];     // segment_sum(x[i0])
__device__ float g_t2  [(size_t)N_NODES * DIM_HEAD];  // segment_sum(t2)
__device__ int   g_indeg[N_NODES];
__device__ float g_xld [(size_t)N_NODES * DIM_HEAD];  // x @ lora_down

// mma-B-fragment swizzled weights (tf32-rounded fp32 bit patterns)
__device__ float g_W2f[36 * 64 * 32 * 2];          // W2 288x512: [ks][col8][lane][2]
__device__ float g_GVf[2 * 8 * 4 * 16 * 32 * 2];   // gate/value kernels
__device__ float g_Pf [8 * 16 * 4 * 32 * 2];       // post kernel
__device__ float g_LDf[32 * 4 * 32 * 2];           // lora_down 256x32

__device__ __forceinline__ float sp(float x) {
    return fmaxf(x, 0.f) + log1pf(expf(-fabsf(x)));
}
__device__ __forceinline__ float wsum(float v) {
#pragma unroll
    for (int o = 16; o; o >>= 1) v += __shfl_xor_sync(0xffffffffu, v, o);
    return v;
}
__device__ __forceinline__ void red_add_v4(float* p, float4 v) {
    asm volatile("red.global.add.v4.f32 [%0], {%1, %2, %3, %4};"
                 :: "l"(p), "f"(v.x), "f"(v.y), "f"(v.z), "f"(v.w)
                 : "memory");
}
__device__ __forceinline__ float tf32r(float f) {
    unsigned r;
    asm("cvt.rna.tf32.f32 %0, %1;" : "=r"(r) : "f"(f));
    return __uint_as_float(r);
}
__device__ __forceinline__ void mma_tf32(float4& c,
    unsigned a0, unsigned a1, unsigned a2, unsigned a3,
    unsigned b0, unsigned b1)
{
    asm volatile(
        "mma.sync.aligned.m16n8k8.row.col.f32.tf32.tf32.f32 "
        "{%0,%1,%2,%3},{%4,%5,%6,%7},{%8,%9},{%0,%1,%2,%3};"
        : "+f"(c.x), "+f"(c.y), "+f"(c.z), "+f"(c.w)
        : "r"(a0), "r"(a1), "r"(a2), "r"(a3), "r"(b0), "r"(b1));
}

// ---------------------------------------------------------------------------
// prep_kernel: zero scratch + compute/swizzle all mma B weights.
// block ranges:
//   [0,144)    W2 = [lin_pre;lora_up]@[gate_lin|value_lin], float4 reg-tiled
//   [144,400)  gate/value kernel swizzle
//   [400,528)  post kernel swizzle
//   [528,560)  lora_down swizzle
//   [560,1584) zero g_aggx / g_t2 / g_indeg
// ---------------------------------------------------------------------------
__global__ __launch_bounds__(256) void prep_kernel(
    const float* __restrict__ lin_pre,
    const float* __restrict__ lora_up,
    const float* __restrict__ gate_lin,
    const float* __restrict__ value_lin,
    const float* __restrict__ gate_kernel,
    const float* __restrict__ value_kernel,
    const float* __restrict__ post_kernel,
    const float* __restrict__ lora_down)
{
    const int b = blockIdx.x, tid = threadIdx.x;
    if (b < 144) {
        int id = b * 256 + tid;            // 36864
        int k  = id >> 7;                  // 0..287
        int n  = (id & 127) * 4;           // 0..508
        const float* srow = (k < 256) ? (lin_pre + k * 256)
                                      : (lora_up + (k - 256) * 256);
        const float* M = (n < 256) ? gate_lin : value_lin;
        int nn = n & 255;
        float4 acc = make_float4(0.f, 0.f, 0.f, 0.f);
#pragma unroll 4
        for (int j = 0; j < 256; j++) {
            float  s = __ldg(&srow[j]);
            float4 m = __ldg((const float4*)(M + j * 256 + nn));
            acc.x += s * m.x; acc.y += s * m.y;
            acc.z += s * m.z; acc.w += s * m.w;
        }
        int ks = k >> 3, kin = k & 7, tig = kin & 3, jj = kin >> 2;
        float v[4] = {acc.x, acc.y, acc.z, acc.w};
#pragma unroll
        for (int q = 0; q < 4; q++) {
            int nq = n + q;
            int idx = ((ks * 64 + (nq >> 3)) * 32 + ((nq & 7) * 4 + tig)) * 2 + jj;
            g_W2f[idx] = tf32r(v[q]);
        }
    } else if (b < 400) {
        int id = (b - 144) * 256 + tid;    // 65536
        int path = id >> 15;
        int h    = (id >> 12) & 7;
        int d    = (id >> 7) & 31;
        int f    = id & 127;
        float val = path ? __ldg(&value_kernel[h * 4096 + d * 128 + f])
                         : __ldg(&gate_kernel [h * 4096 + d * 128 + f]);
        int ks = d >> 3, kin = d & 7, tig = kin & 3, jj = kin >> 2;
        int nt = f >> 3, g = f & 7;
        int idx = (((((path * 8 + h) * 4 + ks) * 16 + nt) * 32) + (g * 4 + tig)) * 2 + jj;
        g_GVf[idx] = tf32r(val);
    } else if (b < 528) {
        int p = (b - 400) * 256 + tid;     // 32768
        int h = p >> 12;
        int f = (p >> 5) & 127;
        int d2 = p & 31;
        float val = __ldg(&post_kernel[h * 4096 + f * 32 + d2]);
        int ks = f >> 3, kin = f & 7, tig = kin & 3, jj = kin >> 2;
        int nt = d2 >> 3, g = d2 & 7;
        int idx = ((((h * 16 + ks) * 4 + nt) * 32) + (g * 4 + tig)) * 2 + jj;
        g_Pf[idx] = tf32r(val);
    } else if (b < 560) {
        int q = (b - 528) * 256 + tid;     // 8192
        int k = q >> 5, n = q & 31;
        float val = __ldg(&lora_down[k * 32 + n]);
        int ks = k >> 3, kin = k & 7, tig = kin & 3, jj = kin >> 2;
        int nt = n >> 3, g = n & 7;
        int idx = (((ks * 4 + nt) * 32) + (g * 4 + tig)) * 2 + jj;
        g_LDf[idx] = tf32r(val);
    } else {
        size_t i0 = (size_t)(b - 560) * 256 + tid;
        size_t step = (size_t)1024 * 256;
        size_t n4 = (size_t)N_NODES * WIDTH / 4;
        float4* p = (float4*)g_aggx;
        for (size_t i = i0; i < n4; i += step)
            p[i] = make_float4(0.f, 0.f, 0.f, 0.f);
        size_t m4 = (size_t)N_NODES * DIM_HEAD / 4;
        float4* q4 = (float4*)g_t2;
        for (size_t i = i0; i < m4; i += step)
            q4[i] = make_float4(0.f, 0.f, 0.f, 0.f);
        for (size_t i = i0; i < N_NODES; i += step)
            g_indeg[i] = 0;
    }
}

// ---------------------------------------------------------------------------
// xld = x @ lora_down  via tf32 mma, 64 rows per block
// ---------------------------------------------------------------------------
__global__ __launch_bounds__(256) void xld_kernel(const float* __restrict__ x)
{
    extern __shared__ float xs[];          // [64][260]
    const int tid = threadIdx.x;
    const int nb  = blockIdx.x * MTILE;
    const int lane = tid & 31, wid = tid >> 5;
    const int g = lane >> 2, t = lane & 3;

    {
        const int n  = tid >> 2;
        const int c0 = (tid & 3) * 4;
        const int gcl = min(nb + n, N_NODES - 1);
        const float* xr = x + (size_t)gcl * WIDTH;
#pragma unroll
        for (int it = 0; it < 16; it++) {
            int c = c0 + it * 16;
            float4 v = __ldg((const float4*)(xr + c));
            xs[n * 260 + c + 0] = tf32r(v.x);
            xs[n * 260 + c + 1] = tf32r(v.y);
            xs[n * 260 + c + 2] = tf32r(v.z);
            xs[n * 260 + c + 3] = tf32r(v.w);
        }
    }
    __syncthreads();

    const int mf = wid >> 1, nh = wid & 1;
    const unsigned* Xu = (const unsigned*)xs;
    const int r = (mf * 16 + g) * 260;
    float4 acc[2] = {make_float4(0,0,0,0), make_float4(0,0,0,0)};
#pragma unroll 4
    for (int ks = 0; ks < 32; ks++) {
        int kc = ks * 8 + t;
        unsigned a0 = Xu[r + kc];
        unsigned a1 = Xu[r + 2080 + kc];
        unsigned a2 = Xu[r + kc + 4];
        unsigned a3 = Xu[r + 2080 + kc + 4];
#pragma unroll
        for (int j = 0; j < 2; j++) {
            int nt = nh * 2 + j;
            uint2 bb = __ldg(((const uint2*)g_LDf) + (ks * 4 + nt) * 32 + lane);
            mma_tf32(acc[j], a0, a1, a2, a3, bb.x, bb.y);
        }
    }
#pragma unroll
    for (int j = 0; j < 2; j++) {
        int col = nh * 16 + j * 8 + 2 * t;
        int row0 = nb + mf * 16 + g;
        if (row0 < N_NODES)
            *(float2*)&g_xld[(size_t)row0 * 32 + col] = make_float2(acc[j].x, acc[j].y);
        if (row0 + 8 < N_NODES)
            *(float2*)&g_xld[(size_t)(row0 + 8) * 32 + col] = make_float2(acc[j].z, acc[j].w);
    }
}

// ---------------------------------------------------------------------------
// Edge kernel: 32 edges per block (unchanged structure)
// ---------------------------------------------------------------------------
__global__ __launch_bounds__(256) void edge_kernel(
    const float* __restrict__ x,
    const int*   __restrict__ edge_idx,
    const int*   __restrict__ edge_attr,
    const float* __restrict__ node_elec,
    const float* __restrict__ emb_edge,
    const float* __restrict__ moa_w,
    const float* __restrict__ moa_s,
    const float* __restrict__ elec_lin)
{
    __shared__ int   s_i0[32], s_i1[32];
    __shared__ float emb_s[32][33];

    const int tid = threadIdx.x;
    const int eb  = blockIdx.x * 32;

    if (tid < 32) {
        int i0 = edge_idx[eb + tid];
        int i1 = edge_idx[N_EDGES + eb + tid];
        s_i0[tid] = i0;
        s_i1[tid] = i1;
        atomicAdd(&g_indeg[i1], 1);
    }
    __syncthreads();

    {
        const int wid = tid >> 5, lane = tid & 31;
        float w0 = sp(moa_w[lane]);
        float w1 = sp(moa_w[32 + lane]);
        w0 /= wsum(w0);
        w1 /= wsum(w1);
        const float s0  = sp(moa_s[lane]);
        const float s1  = sp(moa_s[32 + lane]);
        const float el0 = elec_lin[lane];
        const float el1 = elec_lin[32 + lane];
#pragma unroll
        for (int i = 0; i < 4; i++) {
            int e  = wid * 4 + i;
            int i0 = s_i0[e], i1 = s_i1[e];
            float d0 = node_elec[2 * i0]     - node_elec[2 * i1];
            float d1 = node_elec[2 * i0 + 1] - node_elec[2 * i1 + 1];
            float m0 = wsum(tanhf(d0 * s0) * w0);
            float m1 = wsum(tanhf(d1 * s1) * w1);
            int ge = eb + e;
            int a0 = edge_attr[3 * ge], a1 = edge_attr[3 * ge + 1], a2 = edge_attr[3 * ge + 2];
            emb_s[e][lane] = emb_edge[a0 * 32 + lane] + emb_edge[a1 * 32 + lane] +
                             emb_edge[a2 * 32 + lane] + m0 * el0 + m1 * el1;
        }
    }
    __syncthreads();

    const int e  = tid >> 3;
    const int i0 = s_i0[e], i1 = s_i1[e];

    {
        const int d = (tid & 7) * 4;
        float4 a = __ldg((const float4*)(g_xld + (size_t)i0 * 32 + d));
        float4 b = __ldg((const float4*)(g_xld + (size_t)i1 * 32 + d));
        float4 t;
        t.x = (a.x + b.x) * emb_s[e][d + 0];
        t.y = (a.y + b.y) * emb_s[e][d + 1];
        t.z = (a.z + b.z) * emb_s[e][d + 2];
        t.w = (a.w + b.w) * emb_s[e][d + 3];
        red_add_v4(g_t2 + (size_t)i1 * 32 + d, t);
    }
    {
        const int c0 = (tid & 7) * 4;
        const float4* xr = (const float4*)(x + (size_t)i0 * WIDTH);
        float* dst = g_aggx + (size_t)i1 * WIDTH;
#pragma unroll
        for (int it = 0; it < 8; it++) {
            int c = c0 + it * 32;
            float4 v = __ldg(&xr[c >> 2]);
            red_add_v4(dst + c, v);
        }
    }
}

// ---------------------------------------------------------------------------
// Node kernel: 64 nodes per block, all GEMMs on mma.tf32
// smem: A_s[64][292] ; u_s[64][260] ; v_s[64][260]
//       avv (two [64][132] head buffers) reuses A_s region
// ---------------------------------------------------------------------------
__global__ __launch_bounds__(256) void node_kernel(
    const float* __restrict__ x,
    const int*   __restrict__ deg,
    const float* __restrict__ emb_deg,
    const float* __restrict__ act_bias,
    float*       __restrict__ out)
{
    extern __shared__ float sm[];
    float* A_s   = sm;                    // [64][292] = 18688 floats
    float* u_s   = sm + 64 * 292;         // [64][260]
    float* v_s   = u_s + 64 * 260;        // [64][260]
    float* avv_s = A_s;                   // 2 x [64][132] = 16896 floats (fits)

    const int tid  = threadIdx.x;
    const int nb   = blockIdx.x * MTILE;
    const int lane = tid & 31, wid = tid >> 5;
    const int g = lane >> 2, t = lane & 3;

    // --- stage inputs (tf32-rounded): raw agg | t2 ---
    {
        const int n  = tid >> 2;
        const int c0 = (tid & 3) * 4;
        const int gcl = min(nb + n, N_NODES - 1);
        const float idg = (float)__ldg(&g_indeg[gcl]);
        const float* ra = g_aggx + (size_t)gcl * WIDTH;
        const float* rx = x + (size_t)gcl * WIDTH;
#pragma unroll
        for (int it = 0; it < 16; it++) {
            int c = c0 + it * 16;
            float4 a  = *(const float4*)(ra + c);
            float4 xv = __ldg((const float4*)(rx + c));
            A_s[n * 292 + c + 0] = tf32r(a.x + idg * xv.x);
            A_s[n * 292 + c + 1] = tf32r(a.y + idg * xv.y);
            A_s[n * 292 + c + 2] = tf32r(a.z + idg * xv.z);
            A_s[n * 292 + c + 3] = tf32r(a.w + idg * xv.w);
        }
    }
#pragma unroll
    for (int it = 0; it < 2; it++) {
        int lin = tid + it * 256;
        int n2 = lin >> 3, d = (lin & 7) * 4;
        int gcl = min(nb + n2, N_NODES - 1);
        float4 t2v = *(const float4*)(g_t2 + (size_t)gcl * 32 + d);
        A_s[n2 * 292 + 256 + d + 0] = tf32r(t2v.x);
        A_s[n2 * 292 + 256 + d + 1] = tf32r(t2v.y);
        A_s[n2 * 292 + 256 + d + 2] = tf32r(t2v.z);
        A_s[n2 * 292 + 256 + d + 3] = tf32r(t2v.w);
    }
    __syncthreads();

    // --- Stage A: [64x288] @ W2[288x512] -> U|V ---
    {
        const unsigned* Au = (const unsigned*)A_s;
        float4 acc[4][8];
#pragma unroll
        for (int mf = 0; mf < 4; mf++)
#pragma unroll
            for (int nt = 0; nt < 8; nt++)
                acc[mf][nt] = make_float4(0.f, 0.f, 0.f, 0.f);

        const uint2* Bp = ((const uint2*)g_W2f) + wid * 8 * 32 + lane;
#pragma unroll 4
        for (int ks = 0; ks < 36; ks++) {
            int kc = ks * 8 + t;
            unsigned a0[4], a1[4], a2[4], a3[4];
#pragma unroll
            for (int mf = 0; mf < 4; mf++) {
                int r = (mf * 16 + g) * 292;
                a0[mf] = Au[r + kc];
                a1[mf] = Au[r + 2336 + kc];        // +8 rows (8*292)
                a2[mf] = Au[r + kc + 4];
                a3[mf] = Au[r + 2336 + kc + 4];
            }
            const uint2* Bks = Bp + ks * 64 * 32;
#pragma unroll
            for (int nt = 0; nt < 8; nt++) {
                uint2 bb = __ldg(Bks + nt * 32);
#pragma unroll
                for (int mf = 0; mf < 4; mf++)
                    mma_tf32(acc[mf][nt], a0[mf], a1[mf], a2[mf], a3[mf], bb.x, bb.y);
            }
        }
        float* dst = (wid < 4) ? u_s : v_s;
        const int cb = (wid & 3) * 64;
#pragma unroll
        for (int mf = 0; mf < 4; mf++)
#pragma unroll
            for (int nt = 0; nt < 8; nt++) {
                int c = cb + nt * 8 + 2 * t;
                int r = (mf * 16 + g) * 260;
                *(float2*)&dst[r + c]        = make_float2(acc[mf][nt].x, acc[mf][nt].y);
                *(float2*)&dst[r + 2080 + c] = make_float2(acc[mf][nt].z, acc[mf][nt].w);
            }
    }
    __syncthreads();

    // --- per-(node,head) RMS norm; gate adds deg-bias, /sqrt2; tf32-round ---
#pragma unroll
    for (int it = 0; it < 2; it++) {
        const int task = it * 256 + tid;
        const int n = task & 63, h = task >> 6;
        const int gcl = min(nb + n, N_NODES - 1);
        const int dd = __ldg(&deg[gcl]);
        const float inv_s2 = 0.70710678118654752440f;

        float4 uu[8];
        float ss = 0.f;
#pragma unroll
        for (int i = 0; i < 8; i++) {
            uu[i] = *(float4*)&u_s[n * 260 + h * 32 + 4 * i];
            ss += uu[i].x * uu[i].x + uu[i].y * uu[i].y +
                  uu[i].z * uu[i].z + uu[i].w * uu[i].w;
        }
        float rinv = rsqrtf(ss * (1.f / 32.f) + 1e-6f);
#pragma unroll
        for (int i = 0; i < 8; i++) {
            float4 b = __ldg((const float4*)(emb_deg + dd * 256 + h * 32 + 4 * i));
            u_s[n * 260 + h * 32 + 4 * i + 0] = tf32r((uu[i].x * rinv + b.x) * inv_s2);
            u_s[n * 260 + h * 32 + 4 * i + 1] = tf32r((uu[i].y * rinv + b.y) * inv_s2);
            u_s[n * 260 + h * 32 + 4 * i + 2] = tf32r((uu[i].z * rinv + b.z) * inv_s2);
            u_s[n * 260 + h * 32 + 4 * i + 3] = tf32r((uu[i].w * rinv + b.w) * inv_s2);
        }
        float4 vv4[8];
        float ssv = 0.f;
#pragma unroll
        for (int i = 0; i < 8; i++) {
            vv4[i] = *(float4*)&v_s[n * 260 + h * 32 + 4 * i];
            ssv += vv4[i].x * vv4[i].x + vv4[i].y * vv4[i].y +
                   vv4[i].z * vv4[i].z + vv4[i].w * vv4[i].w;
        }
        float rinvv = rsqrtf(ssv * (1.f / 32.f) + 1e-6f);
#pragma unroll
        for (int i = 0; i < 8; i++) {
            v_s[n * 260 + h * 32 + 4 * i + 0] = tf32r(vv4[i].x * rinvv);
            v_s[n * 260 + h * 32 + 4 * i + 1] = tf32r(vv4[i].y * rinvv);
            v_s[n * 260 + h * 32 + 4 * i + 2] = tf32r(vv4[i].z * rinvv);
            v_s[n * 260 + h * 32 + 4 * i + 3] = tf32r(vv4[i].w * rinvv);
        }
    }
    __syncthreads();

    const float CLIP_LO = 0.22360679774997896f;
    const float CLIP_HI = 4.47213595499957939f;
    const unsigned* U32 = (const unsigned*)u_s;
    const unsigned* V32 = (const unsigned*)v_s;

#pragma unroll 1
    for (int hp = 0; hp < 4; hp++) {
        // --- Stage B: gate & value head GEMMs for head pair ---
#pragma unroll
        for (int sub = 0; sub < 2; sub++) {
            const int h = hp * 2 + sub;
            float* avv = avv_s + sub * (64 * 132);
            float4 ag[4][2], av4[4][2];
#pragma unroll
            for (int mf = 0; mf < 4; mf++)
#pragma unroll
                for (int j = 0; j < 2; j++) {
                    ag[mf][j]  = make_float4(0.f, 0.f, 0.f, 0.f);
                    av4[mf][j] = make_float4(0.f, 0.f, 0.f, 0.f);
                }
#pragma unroll
            for (int ks = 0; ks < 4; ks++) {
                int col = h * 32 + ks * 8 + t;
                unsigned ua0[4], ua1[4], ua2[4], ua3[4];
                unsigned va0[4], va1[4], va2[4], va3[4];
#pragma unroll
                for (int mf = 0; mf < 4; mf++) {
                    int r = (mf * 16 + g) * 260;
                    ua0[mf] = U32[r + col];        ua1[mf] = U32[r + 2080 + col];
                    ua2[mf] = U32[r + col + 4];    ua3[mf] = U32[r + 2080 + col + 4];
                    va0[mf] = V32[r + col];        va1[mf] = V32[r + 2080 + col];
                    va2[mf] = V32[r + col + 4];    va3[mf] = V32[r + 2080 + col + 4];
                }
#pragma unroll
                for (int j = 0; j < 2; j++) {
                    int nt16 = wid * 2 + j;
                    uint2 bg = __ldg(((const uint2*)g_GVf) +
                                     ((h * 4 + ks) * 16 + nt16) * 32 + lane);
                    uint2 bv = __ldg(((const uint2*)g_GVf) +
                                     (((8 + h) * 4 + ks) * 16 + nt16) * 32 + lane);
#pragma unroll
                    for (int mf = 0; mf < 4; mf++) {
                        mma_tf32(ag[mf][j],  ua0[mf], ua1[mf], ua2[mf], ua3[mf], bg.x, bg.y);
                        mma_tf32(av4[mf][j], va0[mf], va1[mf], va2[mf], va3[mf], bv.x, bv.y);
                    }
                }
            }
#pragma unroll
            for (int j = 0; j < 2; j++) {
                int c = wid * 16 + j * 8 + 2 * t;
                float2 bias = __ldg((const float2*)(act_bias + h * 128 + c));
#pragma unroll
                for (int mf = 0; mf < 4; mf++) {
                    int r = (mf * 16 + g) * 132;
                    float o0 = fminf(fmaxf(sp(ag[mf][j].x + bias.x), CLIP_LO), CLIP_HI) * av4[mf][j].x;
                    float o1 = fminf(fmaxf(sp(ag[mf][j].y + bias.y), CLIP_LO), CLIP_HI) * av4[mf][j].y;
                    float o2 = fminf(fmaxf(sp(ag[mf][j].z + bias.x), CLIP_LO), CLIP_HI) * av4[mf][j].z;
                    float o3 = fminf(fmaxf(sp(ag[mf][j].w + bias.y), CLIP_LO), CLIP_HI) * av4[mf][j].w;
                    avv[r + c + 0]        = tf32r(o0);
                    avv[r + c + 1]        = tf32r(o1);
                    avv[r + 1056 + c + 0] = tf32r(o2);
                    avv[r + 1056 + c + 1] = tf32r(o3);
                }
            }
        }
        __syncthreads();

        // --- Stage D: out_h = avv[64x128] @ post_kernel[h][128x32] ---
        {
            const int h  = hp * 2 + (wid >> 2);
            const unsigned* AV = (const unsigned*)(avv_s + (wid >> 2) * (64 * 132));
            const int c8 = wid & 3;
            float4 dacc[4];
#pragma unroll
            for (int mf = 0; mf < 4; mf++) dacc[mf] = make_float4(0.f, 0.f, 0.f, 0.f);
#pragma unroll
            for (int ks = 0; ks < 16; ks++) {
                int kc = ks * 8 + t;
                uint2 bb = __ldg(((const uint2*)g_Pf) +
                                 ((h * 16 + ks) * 4 + c8) * 32 + lane);
#pragma unroll
                for (int mf = 0; mf < 4; mf++) {
                    int r = (mf * 16 + g) * 132;
                    mma_tf32(dacc[mf], AV[r + kc], AV[r + 1056 + kc],
                             AV[r + kc + 4], AV[r + 1056 + kc + 4], bb.x, bb.y);
                }
            }
            int col = h * 32 + c8 * 8 + 2 * t;
#pragma unroll
            for (int mf = 0; mf < 4; mf++) {
                int row0 = nb + mf * 16 + g;
                if (row0 < N_NODES)
                    *(float2*)&out[(size_t)row0 * WIDTH + col] =
                        make_float2(dacc[mf].x, dacc[mf].y);
                if (row0 + 8 < N_NODES)
                    *(float2*)&out[(size_t)(row0 + 8) * WIDTH + col] =
                        make_float2(dacc[mf].z, dacc[mf].w);
            }
        }
        __syncthreads();
    }
}

// ---------------------------------------------------------------------------
// Launch
// ---------------------------------------------------------------------------
extern "C" void kernel_launch(void* const* d_in, const int* in_sizes, int n_in,
                              void* d_out, int out_size) {
    const float* x            = (const float*)d_in[0];
    const int*   deg          = (const int*)  d_in[1];
    const int*   edge_idx     = (const int*)  d_in[2];
    const int*   edge_attr    = (const int*)  d_in[3];
    const float* node_elec    = (const float*)d_in[4];
    const float* lora_down    = (const float*)d_in[5];
    const float* lora_up      = (const float*)d_in[6];
    const float* emb_edge     = (const float*)d_in[7];
    const float* moa_w        = (const float*)d_in[8];
    const float* moa_s        = (const float*)d_in[9];
    const float* elec_lin     = (const float*)d_in[10];
    const float* emb_deg      = (const float*)d_in[11];
    const float* lin_pre      = (const float*)d_in[12];
    const float* gate_lin     = (const float*)d_in[13];
    const float* gate_kernel  = (const float*)d_in[14];
    const float* value_lin    = (const float*)d_in[15];
    const float* value_kernel = (const float*)d_in[16];
    const float* act_bias     = (const float*)d_in[17];
    const float* post_kernel  = (const float*)d_in[18];
    float* out = (float*)d_out;

    const int nblocks = (N_NODES + MTILE - 1) / MTILE;   // 938

    prep_kernel<<<1584, 256>>>(lin_pre, lora_up, gate_lin, value_lin,
                               gate_kernel, value_kernel, post_kernel, lora_down);

    size_t xsm = (size_t)64 * 260 * sizeof(float);       // 66560 B
    cudaFuncSetAttribute(xld_kernel,
                         cudaFuncAttributeMaxDynamicSharedMemorySize, (int)xsm);
    xld_kernel<<<nblocks, 256, xsm>>>(x);

    edge_kernel<<<N_EDGES / 32, 256>>>(
        x, edge_idx, edge_attr, node_elec,
        emb_edge, moa_w, moa_s, elec_lin);

    size_t nsm = ((size_t)64 * 292 + 2 * 64 * 260) * sizeof(float);  // 207872 B
    cudaFuncSetAttribute(node_kernel,
                         cudaFuncAttributeMaxDynamicSharedMemorySize, (int)nsm);
    node_kernel<<<nblocks, 256, nsm>>>(
        x, deg, emb_deg, act_bias, out);
}

// round 7
// speedup vs baseline: 5.0167x; 1.0910x over previous
#include <cuda_runtime.h>
#include <cstddef>

#define N_NODES   60000
#define N_EDGES   240000
#define WIDTH     256
#define DIM_HEAD  32
#define NUM_HEAD  8
#define MTILE     64

// ---------------------------------------------------------------------------
// Device scratch
// ---------------------------------------------------------------------------
__device__ float g_aggx[(size_t)N_NODES * WIDTH];     // segment_sum(x[i0])
__device__ float g_t2  [(size_t)N_NODES * DIM_HEAD];  // segment_sum(t2)
__device__ int   g_indeg[N_NODES];
__device__ float g_xld [(size_t)N_NODES * DIM_HEAD];  // x @ lora_down

// mma-B-fragment swizzled weights (tf32-rounded fp32 bit patterns)
__device__ float g_W2f[36 * 64 * 32 * 2];          // W2 288x512: [ks][col8][lane][2]
__device__ float g_GVf[2 * 8 * 4 * 16 * 32 * 2];   // gate/value kernels
__device__ float g_Pf [8 * 16 * 4 * 32 * 2];       // post kernel
__device__ float g_LDf[32 * 4 * 32 * 2];           // lora_down 256x32

__device__ __forceinline__ float sp(float x) {
    return fmaxf(x, 0.f) + log1pf(expf(-fabsf(x)));
}
__device__ __forceinline__ float wsum(float v) {
#pragma unroll
    for (int o = 16; o; o >>= 1) v += __shfl_xor_sync(0xffffffffu, v, o);
    return v;
}
__device__ __forceinline__ void red_add_v4(float* p, float4 v) {
    asm volatile("red.global.add.v4.f32 [%0], {%1, %2, %3, %4};"
                 :: "l"(p), "f"(v.x), "f"(v.y), "f"(v.z), "f"(v.w)
                 : "memory");
}
__device__ __forceinline__ float tf32r(float f) {
    unsigned r;
    asm("cvt.rna.tf32.f32 %0, %1;" : "=r"(r) : "f"(f));
    return __uint_as_float(r);
}
__device__ __forceinline__ void mma_tf32(float4& c,
    unsigned a0, unsigned a1, unsigned a2, unsigned a3,
    unsigned b0, unsigned b1)
{
    asm volatile(
        "mma.sync.aligned.m16n8k8.row.col.f32.tf32.tf32.f32 "
        "{%0,%1,%2,%3},{%4,%5,%6,%7},{%8,%9},{%0,%1,%2,%3};"
        : "+f"(c.x), "+f"(c.y), "+f"(c.z), "+f"(c.w)
        : "r"(a0), "r"(a1), "r"(a2), "r"(a3), "r"(b0), "r"(b1));
}

// ---------------------------------------------------------------------------
// prep_kernel: zero scratch + compute/swizzle all mma B weights.
// ---------------------------------------------------------------------------
__global__ __launch_bounds__(256) void prep_kernel(
    const float* __restrict__ lin_pre,
    const float* __restrict__ lora_up,
    const float* __restrict__ gate_lin,
    const float* __restrict__ value_lin,
    const float* __restrict__ gate_kernel,
    const float* __restrict__ value_kernel,
    const float* __restrict__ post_kernel,
    const float* __restrict__ lora_down)
{
    const int b = blockIdx.x, tid = threadIdx.x;
    if (b < 144) {
        int id = b * 256 + tid;            // 36864
        int k  = id >> 7;                  // 0..287
        int n  = (id & 127) * 4;           // 0..508
        const float* srow = (k < 256) ? (lin_pre + k * 256)
                                      : (lora_up + (k - 256) * 256);
        const float* M = (n < 256) ? gate_lin : value_lin;
        int nn = n & 255;
        float4 acc = make_float4(0.f, 0.f, 0.f, 0.f);
#pragma unroll 4
        for (int j = 0; j < 256; j++) {
            float  s = __ldg(&srow[j]);
            float4 m = __ldg((const float4*)(M + j * 256 + nn));
            acc.x += s * m.x; acc.y += s * m.y;
            acc.z += s * m.z; acc.w += s * m.w;
        }
        int ks = k >> 3, kin = k & 7, tig = kin & 3, jj = kin >> 2;
        float v[4] = {acc.x, acc.y, acc.z, acc.w};
#pragma unroll
        for (int q = 0; q < 4; q++) {
            int nq = n + q;
            int idx = ((ks * 64 + (nq >> 3)) * 32 + ((nq & 7) * 4 + tig)) * 2 + jj;
            g_W2f[idx] = tf32r(v[q]);
        }
    } else if (b < 400) {
        int id = (b - 144) * 256 + tid;    // 65536
        int path = id >> 15;
        int h    = (id >> 12) & 7;
        int d    = (id >> 7) & 31;
        int f    = id & 127;
        float val = path ? __ldg(&value_kernel[h * 4096 + d * 128 + f])
                         : __ldg(&gate_kernel [h * 4096 + d * 128 + f]);
        int ks = d >> 3, kin = d & 7, tig = kin & 3, jj = kin >> 2;
        int nt = f >> 3, g = f & 7;
        int idx = (((((path * 8 + h) * 4 + ks) * 16 + nt) * 32) + (g * 4 + tig)) * 2 + jj;
        g_GVf[idx] = tf32r(val);
    } else if (b < 528) {
        int p = (b - 400) * 256 + tid;     // 32768
        int h = p >> 12;
        int f = (p >> 5) & 127;
        int d2 = p & 31;
        float val = __ldg(&post_kernel[h * 4096 + f * 32 + d2]);
        int ks = f >> 3, kin = f & 7, tig = kin & 3, jj = kin >> 2;
        int nt = d2 >> 3, g = d2 & 7;
        int idx = ((((h * 16 + ks) * 4 + nt) * 32) + (g * 4 + tig)) * 2 + jj;
        g_Pf[idx] = tf32r(val);
    } else if (b < 560) {
        int q = (b - 528) * 256 + tid;     // 8192
        int k = q >> 5, n = q & 31;
        float val = __ldg(&lora_down[k * 32 + n]);
        int ks = k >> 3, kin = k & 7, tig = kin & 3, jj = kin >> 2;
        int nt = n >> 3, g = n & 7;
        int idx = (((ks * 4 + nt) * 32) + (g * 4 + tig)) * 2 + jj;
        g_LDf[idx] = tf32r(val);
    } else {
        size_t i0 = (size_t)(b - 560) * 256 + tid;
        size_t step = (size_t)1024 * 256;
        size_t n4 = (size_t)N_NODES * WIDTH / 4;
        float4* p = (float4*)g_aggx;
        for (size_t i = i0; i < n4; i += step)
            p[i] = make_float4(0.f, 0.f, 0.f, 0.f);
        size_t m4 = (size_t)N_NODES * DIM_HEAD / 4;
        float4* q4 = (float4*)g_t2;
        for (size_t i = i0; i < m4; i += step)
            q4[i] = make_float4(0.f, 0.f, 0.f, 0.f);
        for (size_t i = i0; i < N_NODES; i += step)
            g_indeg[i] = 0;
    }
}

// ---------------------------------------------------------------------------
// xld = x @ lora_down  via tf32 mma, 64 rows per block
// ---------------------------------------------------------------------------
__global__ __launch_bounds__(256) void xld_kernel(const float* __restrict__ x)
{
    extern __shared__ float xs[];          // [64][260]
    const int tid = threadIdx.x;
    const int nb  = blockIdx.x * MTILE;
    const int lane = tid & 31, wid = tid >> 5;
    const int g = lane >> 2, t = lane & 3;

    {
        const int n  = tid >> 2;
        const int c0 = (tid & 3) * 4;
        const int gcl = min(nb + n, N_NODES - 1);
        const float* xr = x + (size_t)gcl * WIDTH;
#pragma unroll
        for (int it = 0; it < 16; it++) {
            int c = c0 + it * 16;
            float4 v = __ldg((const float4*)(xr + c));
            xs[n * 260 + c + 0] = tf32r(v.x);
            xs[n * 260 + c + 1] = tf32r(v.y);
            xs[n * 260 + c + 2] = tf32r(v.z);
            xs[n * 260 + c + 3] = tf32r(v.w);
        }
    }
    __syncthreads();

    const int mf = wid >> 1, nh = wid & 1;
    const unsigned* Xu = (const unsigned*)xs;
    const int r = (mf * 16 + g) * 260;
    float4 acc[2] = {make_float4(0,0,0,0), make_float4(0,0,0,0)};
#pragma unroll 4
    for (int ks = 0; ks < 32; ks++) {
        int kc = ks * 8 + t;
        unsigned a0 = Xu[r + kc];
        unsigned a1 = Xu[r + 2080 + kc];
        unsigned a2 = Xu[r + kc + 4];
        unsigned a3 = Xu[r + 2080 + kc + 4];
#pragma unroll
        for (int j = 0; j < 2; j++) {
            int nt = nh * 2 + j;
            uint2 bb = __ldg(((const uint2*)g_LDf) + (ks * 4 + nt) * 32 + lane);
            mma_tf32(acc[j], a0, a1, a2, a3, bb.x, bb.y);
        }
    }
#pragma unroll
    for (int j = 0; j < 2; j++) {
        int col = nh * 16 + j * 8 + 2 * t;
        int row0 = nb + mf * 16 + g;
        if (row0 < N_NODES)
            *(float2*)&g_xld[(size_t)row0 * 32 + col] = make_float2(acc[j].x, acc[j].y);
        if (row0 + 8 < N_NODES)
            *(float2*)&g_xld[(size_t)(row0 + 8) * 32 + col] = make_float2(acc[j].z, acc[j].w);
    }
}

// ---------------------------------------------------------------------------
// Edge kernel: 32 edges per block
// ---------------------------------------------------------------------------
__global__ __launch_bounds__(256) void edge_kernel(
    const float* __restrict__ x,
    const int*   __restrict__ edge_idx,
    const int*   __restrict__ edge_attr,
    const float* __restrict__ node_elec,
    const float* __restrict__ emb_edge,
    const float* __restrict__ moa_w,
    const float* __restrict__ moa_s,
    const float* __restrict__ elec_lin)
{
    __shared__ int   s_i0[32], s_i1[32];
    __shared__ float emb_s[32][33];

    const int tid = threadIdx.x;
    const int eb  = blockIdx.x * 32;

    if (tid < 32) {
        int i0 = edge_idx[eb + tid];
        int i1 = edge_idx[N_EDGES + eb + tid];
        s_i0[tid] = i0;
        s_i1[tid] = i1;
        atomicAdd(&g_indeg[i1], 1);
    }
    __syncthreads();

    {
        const int wid = tid >> 5, lane = tid & 31;
        float w0 = sp(moa_w[lane]);
        float w1 = sp(moa_w[32 + lane]);
        w0 /= wsum(w0);
        w1 /= wsum(w1);
        const float s0  = sp(moa_s[lane]);
        const float s1  = sp(moa_s[32 + lane]);
        const float el0 = elec_lin[lane];
        const float el1 = elec_lin[32 + lane];
#pragma unroll
        for (int i = 0; i < 4; i++) {
            int e  = wid * 4 + i;
            int i0 = s_i0[e], i1 = s_i1[e];
            float d0 = node_elec[2 * i0]     - node_elec[2 * i1];
            float d1 = node_elec[2 * i0 + 1] - node_elec[2 * i1 + 1];
            float m0 = wsum(tanhf(d0 * s0) * w0);
            float m1 = wsum(tanhf(d1 * s1) * w1);
            int ge = eb + e;
            int a0 = edge_attr[3 * ge], a1 = edge_attr[3 * ge + 1], a2 = edge_attr[3 * ge + 2];
            emb_s[e][lane] = emb_edge[a0 * 32 + lane] + emb_edge[a1 * 32 + lane] +
                             emb_edge[a2 * 32 + lane] + m0 * el0 + m1 * el1;
        }
    }
    __syncthreads();

    const int e  = tid >> 3;
    const int i0 = s_i0[e], i1 = s_i1[e];

    {
        const int d = (tid & 7) * 4;
        float4 a = __ldg((const float4*)(g_xld + (size_t)i0 * 32 + d));
        float4 b = __ldg((const float4*)(g_xld + (size_t)i1 * 32 + d));
        float4 t;
        t.x = (a.x + b.x) * emb_s[e][d + 0];
        t.y = (a.y + b.y) * emb_s[e][d + 1];
        t.z = (a.z + b.z) * emb_s[e][d + 2];
        t.w = (a.w + b.w) * emb_s[e][d + 3];
        red_add_v4(g_t2 + (size_t)i1 * 32 + d, t);
    }
    {
        const int c0 = (tid & 7) * 4;
        const float4* xr = (const float4*)(x + (size_t)i0 * WIDTH);
        float* dst = g_aggx + (size_t)i1 * WIDTH;
#pragma unroll
        for (int it = 0; it < 8; it++) {
            int c = c0 + it * 32;
            float4 v = __ldg(&xr[c >> 2]);
            red_add_v4(dst + c, v);
        }
    }
}

// ---------------------------------------------------------------------------
// Node kernel: 64 nodes per block, 512 threads (16 warps), all GEMMs mma.tf32
// smem: A_s[64][292] ; u_s[64][260] ; v_s[64][260]
//       avv (two [64][132] head buffers) reuses A_s region
// ---------------------------------------------------------------------------
__global__ __launch_bounds__(512) void node_kernel(
    const float* __restrict__ x,
    const int*   __restrict__ deg,
    const float* __restrict__ emb_deg,
    const float* __restrict__ act_bias,
    float*       __restrict__ out)
{
    extern __shared__ float sm[];
    float* A_s   = sm;                    // [64][292]
    float* u_s   = sm + 64 * 292;         // [64][260]
    float* v_s   = u_s + 64 * 260;        // [64][260]
    float* avv_s = A_s;                   // 2 x [64][132]

    const int tid  = threadIdx.x;
    const int nb   = blockIdx.x * MTILE;
    const int lane = tid & 31, wid = tid >> 5;
    const int g = lane >> 2, t = lane & 3;

    // --- stage inputs (tf32-rounded): raw agg | t2 ---
    {
        const int n  = tid >> 3;
        const int c0 = (tid & 7) * 4;
        const int gcl = min(nb + n, N_NODES - 1);
        const float idg = (float)__ldg(&g_indeg[gcl]);
        const float* ra = g_aggx + (size_t)gcl * WIDTH;
        const float* rx = x + (size_t)gcl * WIDTH;
#pragma unroll
        for (int it = 0; it < 8; it++) {
            int c = c0 + it * 32;
            float4 a  = *(const float4*)(ra + c);
            float4 xv = __ldg((const float4*)(rx + c));
            A_s[n * 292 + c + 0] = tf32r(a.x + idg * xv.x);
            A_s[n * 292 + c + 1] = tf32r(a.y + idg * xv.y);
            A_s[n * 292 + c + 2] = tf32r(a.z + idg * xv.z);
            A_s[n * 292 + c + 3] = tf32r(a.w + idg * xv.w);
        }
        if (tid < 512) {
            int n2 = tid >> 3;
            int d  = (tid & 7) * 4;
            int gc2 = min(nb + n2, N_NODES - 1);
            float4 t2v = *(const float4*)(g_t2 + (size_t)gc2 * 32 + d);
            A_s[n2 * 292 + 256 + d + 0] = tf32r(t2v.x);
            A_s[n2 * 292 + 256 + d + 1] = tf32r(t2v.y);
            A_s[n2 * 292 + 256 + d + 2] = tf32r(t2v.z);
            A_s[n2 * 292 + 256 + d + 3] = tf32r(t2v.w);
        }
    }
    __syncthreads();

    // --- Stage A: [64x288] @ W2[288x512] -> U|V  (16 warps: 2 M x 8 N) ---
    {
        const int wm = wid >> 3, wn = wid & 7;
        const unsigned* Au = (const unsigned*)A_s;
        float4 acc[2][8];
#pragma unroll
        for (int mf = 0; mf < 2; mf++)
#pragma unroll
            for (int nt = 0; nt < 8; nt++)
                acc[mf][nt] = make_float4(0.f, 0.f, 0.f, 0.f);

        const uint2* Bp = ((const uint2*)g_W2f) + (wn * 8) * 32 + lane;
#pragma unroll 4
        for (int ks = 0; ks < 36; ks++) {
            int kc = ks * 8 + t;
            unsigned a0[2], a1[2], a2[2], a3[2];
#pragma unroll
            for (int mf = 0; mf < 2; mf++) {
                int r = (wm * 32 + mf * 16 + g) * 292;
                a0[mf] = Au[r + kc];
                a1[mf] = Au[r + 2336 + kc];        // +8 rows
                a2[mf] = Au[r + kc + 4];
                a3[mf] = Au[r + 2336 + kc + 4];
            }
            const uint2* Bks = Bp + ks * 64 * 32;
#pragma unroll
            for (int nt = 0; nt < 8; nt++) {
                uint2 bb = __ldg(Bks + nt * 32);
#pragma unroll
                for (int mf = 0; mf < 2; mf++)
                    mma_tf32(acc[mf][nt], a0[mf], a1[mf], a2[mf], a3[mf], bb.x, bb.y);
            }
        }
        float* dst = (wn < 4) ? u_s : v_s;
        const int cb = (wn & 3) * 64;
#pragma unroll
        for (int mf = 0; mf < 2; mf++)
#pragma unroll
            for (int nt = 0; nt < 8; nt++) {
                int c = cb + nt * 8 + 2 * t;
                int r = (wm * 32 + mf * 16 + g) * 260;
                *(float2*)&dst[r + c]        = make_float2(acc[mf][nt].x, acc[mf][nt].y);
                *(float2*)&dst[r + 2080 + c] = make_float2(acc[mf][nt].z, acc[mf][nt].w);
            }
    }
    __syncthreads();

    // --- per-(node,head) RMS norm; one task per thread ---
    {
        const int n = tid & 63, h = tid >> 6;
        const int gcl = min(nb + n, N_NODES - 1);
        const int dd = __ldg(&deg[gcl]);
        const float inv_s2 = 0.70710678118654752440f;

        float4 uu[8];
        float ss = 0.f;
#pragma unroll
        for (int i = 0; i < 8; i++) {
            uu[i] = *(float4*)&u_s[n * 260 + h * 32 + 4 * i];
            ss += uu[i].x * uu[i].x + uu[i].y * uu[i].y +
                  uu[i].z * uu[i].z + uu[i].w * uu[i].w;
        }
        float rinv = rsqrtf(ss * (1.f / 32.f) + 1e-6f);
#pragma unroll
        for (int i = 0; i < 8; i++) {
            float4 b = __ldg((const float4*)(emb_deg + dd * 256 + h * 32 + 4 * i));
            u_s[n * 260 + h * 32 + 4 * i + 0] = tf32r((uu[i].x * rinv + b.x) * inv_s2);
            u_s[n * 260 + h * 32 + 4 * i + 1] = tf32r((uu[i].y * rinv + b.y) * inv_s2);
            u_s[n * 260 + h * 32 + 4 * i + 2] = tf32r((uu[i].z * rinv + b.z) * inv_s2);
            u_s[n * 260 + h * 32 + 4 * i + 3] = tf32r((uu[i].w * rinv + b.w) * inv_s2);
        }
        float4 vv4[8];
        float ssv = 0.f;
#pragma unroll
        for (int i = 0; i < 8; i++) {
            vv4[i] = *(float4*)&v_s[n * 260 + h * 32 + 4 * i];
            ssv += vv4[i].x * vv4[i].x + vv4[i].y * vv4[i].y +
                   vv4[i].z * vv4[i].z + vv4[i].w * vv4[i].w;
        }
        float rinvv = rsqrtf(ssv * (1.f / 32.f) + 1e-6f);
#pragma unroll
        for (int i = 0; i < 8; i++) {
            v_s[n * 260 + h * 32 + 4 * i + 0] = tf32r(vv4[i].x * rinvv);
            v_s[n * 260 + h * 32 + 4 * i + 1] = tf32r(vv4[i].y * rinvv);
            v_s[n * 260 + h * 32 + 4 * i + 2] = tf32r(vv4[i].z * rinvv);
            v_s[n * 260 + h * 32 + 4 * i + 3] = tf32r(vv4[i].w * rinvv);
        }
    }
    __syncthreads();

    const float CLIP_LO = 0.22360679774997896f;
    const float CLIP_HI = 4.47213595499957939f;
    const unsigned* U32 = (const unsigned*)u_s;
    const unsigned* V32 = (const unsigned*)v_s;

#pragma unroll 1
    for (int hp = 0; hp < 4; hp++) {
        // --- Stage B: 16 warps = 2 heads x 2 Mhalf x 4 Nquarter ---
        {
            const int sub = wid >> 3;            // head in pair
            const int mh  = (wid >> 2) & 1;      // M half
            const int nq  = wid & 3;             // 32-col quarter of 128
            const int h   = hp * 2 + sub;
            float* avv = avv_s + sub * (64 * 132);

            float4 ag[2][4], av4[2][4];
#pragma unroll
            for (int mf = 0; mf < 2; mf++)
#pragma unroll
                for (int j = 0; j < 4; j++) {
                    ag[mf][j]  = make_float4(0.f, 0.f, 0.f, 0.f);
                    av4[mf][j] = make_float4(0.f, 0.f, 0.f, 0.f);
                }
#pragma unroll
            for (int ks = 0; ks < 4; ks++) {
                int col = h * 32 + ks * 8 + t;
                unsigned ua0[2], ua1[2], ua2[2], ua3[2];
                unsigned va0[2], va1[2], va2[2], va3[2];
#pragma unroll
                for (int mf = 0; mf < 2; mf++) {
                    int r = (mh * 32 + mf * 16 + g) * 260;
                    ua0[mf] = U32[r + col];        ua1[mf] = U32[r + 2080 + col];
                    ua2[mf] = U32[r + col + 4];    ua3[mf] = U32[r + 2080 + col + 4];
                    va0[mf] = V32[r + col];        va1[mf] = V32[r + 2080 + col];
                    va2[mf] = V32[r + col + 4];    va3[mf] = V32[r + 2080 + col + 4];
                }
#pragma unroll
                for (int j = 0; j < 4; j++) {
                    int nt16 = nq * 4 + j;
                    uint2 bg = __ldg(((const uint2*)g_GVf) +
                                     ((h * 4 + ks) * 16 + nt16) * 32 + lane);
                    uint2 bv = __ldg(((const uint2*)g_GVf) +
                                     (((8 + h) * 4 + ks) * 16 + nt16) * 32 + lane);
#pragma unroll
                    for (int mf = 0; mf < 2; mf++) {
                        mma_tf32(ag[mf][j],  ua0[mf], ua1[mf], ua2[mf], ua3[mf], bg.x, bg.y);
                        mma_tf32(av4[mf][j], va0[mf], va1[mf], va2[mf], va3[mf], bv.x, bv.y);
                    }
                }
            }
#pragma unroll
            for (int j = 0; j < 4; j++) {
                int c = nq * 32 + j * 8 + 2 * t;
                float2 bias = __ldg((const float2*)(act_bias + h * 128 + c));
#pragma unroll
                for (int mf = 0; mf < 2; mf++) {
                    int r = (mh * 32 + mf * 16 + g) * 132;
                    float o0 = fminf(fmaxf(sp(ag[mf][j].x + bias.x), CLIP_LO), CLIP_HI) * av4[mf][j].x;
                    float o1 = fminf(fmaxf(sp(ag[mf][j].y + bias.y), CLIP_LO), CLIP_HI) * av4[mf][j].y;
                    float o2 = fminf(fmaxf(sp(ag[mf][j].z + bias.x), CLIP_LO), CLIP_HI) * av4[mf][j].z;
                    float o3 = fminf(fmaxf(sp(ag[mf][j].w + bias.y), CLIP_LO), CLIP_HI) * av4[mf][j].w;
                    avv[r + c + 0]        = tf32r(o0);
                    avv[r + c + 1]        = tf32r(o1);
                    avv[r + 1056 + c + 0] = tf32r(o2);
                    avv[r + 1056 + c + 1] = tf32r(o3);
                }
            }
        }
        __syncthreads();

        // --- Stage D: 16 warps = 2 heads x 2 Mhalf x 4 col8 ---
        {
            const int sub = wid >> 3;
            const int mh  = (wid >> 2) & 1;
            const int c8  = wid & 3;
            const int h   = hp * 2 + sub;
            const unsigned* AV = (const unsigned*)(avv_s + sub * (64 * 132));
            float4 dacc[2];
#pragma unroll
            for (int mf = 0; mf < 2; mf++) dacc[mf] = make_float4(0.f, 0.f, 0.f, 0.f);
#pragma unroll
            for (int ks = 0; ks < 16; ks++) {
                int kc = ks * 8 + t;
                uint2 bb = __ldg(((const uint2*)g_Pf) +
                                 ((h * 16 + ks) * 4 + c8) * 32 + lane);
#pragma unroll
                for (int mf = 0; mf < 2; mf++) {
                    int r = (mh * 32 + mf * 16 + g) * 132;
                    mma_tf32(dacc[mf], AV[r + kc], AV[r + 1056 + kc],
                             AV[r + kc + 4], AV[r + 1056 + kc + 4], bb.x, bb.y);
                }
            }
            int col = h * 32 + c8 * 8 + 2 * t;
#pragma unroll
            for (int mf = 0; mf < 2; mf++) {
                int row0 = nb + mh * 32 + mf * 16 + g;
                if (row0 < N_NODES)
                    *(float2*)&out[(size_t)row0 * WIDTH + col] =
                        make_float2(dacc[mf].x, dacc[mf].y);
                if (row0 + 8 < N_NODES)
                    *(float2*)&out[(size_t)(row0 + 8) * WIDTH + col] =
                        make_float2(dacc[mf].z, dacc[mf].w);
            }
        }
        __syncthreads();
    }
}

// ---------------------------------------------------------------------------
// Launch
// ---------------------------------------------------------------------------
extern "C" void kernel_launch(void* const* d_in, const int* in_sizes, int n_in,
                              void* d_out, int out_size) {
    const float* x            = (const float*)d_in[0];
    const int*   deg          = (const int*)  d_in[1];
    const int*   edge_idx     = (const int*)  d_in[2];
    const int*   edge_attr    = (const int*)  d_in[3];
    const float* node_elec    = (const float*)d_in[4];
    const float* lora_down    = (const float*)d_in[5];
    const float* lora_up      = (const float*)d_in[6];
    const float* emb_edge     = (const float*)d_in[7];
    const float* moa_w        = (const float*)d_in[8];
    const float* moa_s        = (const float*)d_in[9];
    const float* elec_lin     = (const float*)d_in[10];
    const float* emb_deg      = (const float*)d_in[11];
    const float* lin_pre      = (const float*)d_in[12];
    const float* gate_lin     = (const float*)d_in[13];
    const float* gate_kernel  = (const float*)d_in[14];
    const float* value_lin    = (const float*)d_in[15];
    const float* value_kernel = (const float*)d_in[16];
    const float* act_bias     = (const float*)d_in[17];
    const float* post_kernel  = (const float*)d_in[18];
    float* out = (float*)d_out;

    const int nblocks = (N_NODES + MTILE - 1) / MTILE;   // 938

    prep_kernel<<<1584, 256>>>(lin_pre, lora_up, gate_lin, value_lin,
                               gate_kernel, value_kernel, post_kernel, lora_down);

    size_t xsm = (size_t)64 * 260 * sizeof(float);       // 66560 B
    cudaFuncSetAttribute(xld_kernel,
                         cudaFuncAttributeMaxDynamicSharedMemorySize, (int)xsm);
    xld_kernel<<<nblocks, 256, xsm>>>(x);

    edge_kernel<<<N_EDGES / 32, 256>>>(
        x, edge_idx, edge_attr, node_elec,
        emb_edge, moa_w, moa_s, elec_lin);

    size_t nsm = ((size_t)64 * 292 + 2 * 64 * 260) * sizeof(float);  // 207872 B
    cudaFuncSetAttribute(node_kernel,
                         cudaFuncAttributeMaxDynamicSharedMemorySize, (int)nsm);
    node_kernel<<<nblocks, 512, nsm>>>(
        x, deg, emb_deg, act_bias, out);
}

// round 8
// speedup vs baseline: 5.4622x; 1.0888x over previous
#include <cuda_runtime.h>
#include <cstddef>

#define N_NODES   60000
#define N_EDGES   240000
#define WIDTH     256
#define DIM_HEAD  32
#define NUM_HEAD  8
#define MTILE     32

// ---------------------------------------------------------------------------
// Device scratch
// ---------------------------------------------------------------------------
__device__ float g_aggx[(size_t)N_NODES * WIDTH];     // segment_sum(x[i0])
__device__ float g_t2  [(size_t)N_NODES * DIM_HEAD];  // segment_sum(t2)
__device__ int   g_indeg[N_NODES];
__device__ float g_xld [(size_t)N_NODES * DIM_HEAD];  // x @ lora_down

// mma-B-fragment swizzled weights (tf32-rounded fp32 bit patterns)
__device__ float g_W2f[36 * 64 * 32 * 2];          // W2 288x512: [ks][col8][lane][2]
__device__ float g_GVf[2 * 8 * 4 * 16 * 32 * 2];   // gate/value kernels
__device__ float g_Pf [8 * 16 * 4 * 32 * 2];       // post kernel
__device__ float g_LDf[32 * 4 * 32 * 2];           // lora_down 256x32

__device__ __forceinline__ float sp(float x) {
    return fmaxf(x, 0.f) + log1pf(expf(-fabsf(x)));
}
__device__ __forceinline__ float wsum(float v) {
#pragma unroll
    for (int o = 16; o; o >>= 1) v += __shfl_xor_sync(0xffffffffu, v, o);
    return v;
}
__device__ __forceinline__ void red_add_v4(float* p, float4 v) {
    asm volatile("red.global.add.v4.f32 [%0], {%1, %2, %3, %4};"
                 :: "l"(p), "f"(v.x), "f"(v.y), "f"(v.z), "f"(v.w)
                 : "memory");
}
__device__ __forceinline__ float tf32r(float f) {
    unsigned r;
    asm("cvt.rna.tf32.f32 %0, %1;" : "=r"(r) : "f"(f));
    return __uint_as_float(r);
}
__device__ __forceinline__ void mma_tf32(float4& c,
    unsigned a0, unsigned a1, unsigned a2, unsigned a3,
    unsigned b0, unsigned b1)
{
    asm volatile(
        "mma.sync.aligned.m16n8k8.row.col.f32.tf32.tf32.f32 "
        "{%0,%1,%2,%3},{%4,%5,%6,%7},{%8,%9},{%0,%1,%2,%3};"
        : "+f"(c.x), "+f"(c.y), "+f"(c.z), "+f"(c.w)
        : "r"(a0), "r"(a1), "r"(a2), "r"(a3), "r"(b0), "r"(b1));
}

// ---------------------------------------------------------------------------
// prep_kernel: zero scratch + compute/swizzle all mma B weights.
// ---------------------------------------------------------------------------
__global__ __launch_bounds__(256) void prep_kernel(
    const float* __restrict__ lin_pre,
    const float* __restrict__ lora_up,
    const float* __restrict__ gate_lin,
    const float* __restrict__ value_lin,
    const float* __restrict__ gate_kernel,
    const float* __restrict__ value_kernel,
    const float* __restrict__ post_kernel,
    const float* __restrict__ lora_down)
{
    const int b = blockIdx.x, tid = threadIdx.x;
    if (b < 144) {
        int id = b * 256 + tid;            // 36864
        int k  = id >> 7;                  // 0..287
        int n  = (id & 127) * 4;           // 0..508
        const float* srow = (k < 256) ? (lin_pre + k * 256)
                                      : (lora_up + (k - 256) * 256);
        const float* M = (n < 256) ? gate_lin : value_lin;
        int nn = n & 255;
        float4 acc = make_float4(0.f, 0.f, 0.f, 0.f);
#pragma unroll 4
        for (int j = 0; j < 256; j++) {
            float  s = __ldg(&srow[j]);
            float4 m = __ldg((const float4*)(M + j * 256 + nn));
            acc.x += s * m.x; acc.y += s * m.y;
            acc.z += s * m.z; acc.w += s * m.w;
        }
        int ks = k >> 3, kin = k & 7, tig = kin & 3, jj = kin >> 2;
        float v[4] = {acc.x, acc.y, acc.z, acc.w};
#pragma unroll
        for (int q = 0; q < 4; q++) {
            int nq = n + q;
            int idx = ((ks * 64 + (nq >> 3)) * 32 + ((nq & 7) * 4 + tig)) * 2 + jj;
            g_W2f[idx] = tf32r(v[q]);
        }
    } else if (b < 400) {
        int id = (b - 144) * 256 + tid;    // 65536
        int path = id >> 15;
        int h    = (id >> 12) & 7;
        int d    = (id >> 7) & 31;
        int f    = id & 127;
        float val = path ? __ldg(&value_kernel[h * 4096 + d * 128 + f])
                         : __ldg(&gate_kernel [h * 4096 + d * 128 + f]);
        int ks = d >> 3, kin = d & 7, tig = kin & 3, jj = kin >> 2;
        int nt = f >> 3, g = f & 7;
        int idx = (((((path * 8 + h) * 4 + ks) * 16 + nt) * 32) + (g * 4 + tig)) * 2 + jj;
        g_GVf[idx] = tf32r(val);
    } else if (b < 528) {
        int p = (b - 400) * 256 + tid;     // 32768
        int h = p >> 12;
        int f = (p >> 5) & 127;
        int d2 = p & 31;
        float val = __ldg(&post_kernel[h * 4096 + f * 32 + d2]);
        int ks = f >> 3, kin = f & 7, tig = kin & 3, jj = kin >> 2;
        int nt = d2 >> 3, g = d2 & 7;
        int idx = ((((h * 16 + ks) * 4 + nt) * 32) + (g * 4 + tig)) * 2 + jj;
        g_Pf[idx] = tf32r(val);
    } else if (b < 560) {
        int q = (b - 528) * 256 + tid;     // 8192
        int k = q >> 5, n = q & 31;
        float val = __ldg(&lora_down[k * 32 + n]);
        int ks = k >> 3, kin = k & 7, tig = kin & 3, jj = kin >> 2;
        int nt = n >> 3, g = n & 7;
        int idx = (((ks * 4 + nt) * 32) + (g * 4 + tig)) * 2 + jj;
        g_LDf[idx] = tf32r(val);
    } else {
        size_t i0 = (size_t)(b - 560) * 256 + tid;
        size_t step = (size_t)1024 * 256;
        size_t n4 = (size_t)N_NODES * WIDTH / 4;
        float4* p = (float4*)g_aggx;
        for (size_t i = i0; i < n4; i += step)
            p[i] = make_float4(0.f, 0.f, 0.f, 0.f);
        size_t m4 = (size_t)N_NODES * DIM_HEAD / 4;
        float4* q4 = (float4*)g_t2;
        for (size_t i = i0; i < m4; i += step)
            q4[i] = make_float4(0.f, 0.f, 0.f, 0.f);
        for (size_t i = i0; i < N_NODES; i += step)
            g_indeg[i] = 0;
    }
}

// ---------------------------------------------------------------------------
// xld = x @ lora_down  via tf32 mma, 64 rows per block
// ---------------------------------------------------------------------------
__global__ __launch_bounds__(256) void xld_kernel(const float* __restrict__ x)
{
    extern __shared__ float xs[];          // [64][260]
    const int tid = threadIdx.x;
    const int nb  = blockIdx.x * 64;
    const int lane = tid & 31, wid = tid >> 5;
    const int g = lane >> 2, t = lane & 3;

    {
        const int n  = tid >> 2;
        const int c0 = (tid & 3) * 4;
        const int gcl = min(nb + n, N_NODES - 1);
        const float* xr = x + (size_t)gcl * WIDTH;
#pragma unroll
        for (int it = 0; it < 16; it++) {
            int c = c0 + it * 16;
            float4 v = __ldg((const float4*)(xr + c));
            xs[n * 260 + c + 0] = tf32r(v.x);
            xs[n * 260 + c + 1] = tf32r(v.y);
            xs[n * 260 + c + 2] = tf32r(v.z);
            xs[n * 260 + c + 3] = tf32r(v.w);
        }
    }
    __syncthreads();

    const int mf = wid >> 1, nh = wid & 1;
    const unsigned* Xu = (const unsigned*)xs;
    const int r = (mf * 16 + g) * 260;
    float4 acc[2] = {make_float4(0,0,0,0), make_float4(0,0,0,0)};
#pragma unroll 4
    for (int ks = 0; ks < 32; ks++) {
        int kc = ks * 8 + t;
        unsigned a0 = Xu[r + kc];
        unsigned a1 = Xu[r + 2080 + kc];
        unsigned a2 = Xu[r + kc + 4];
        unsigned a3 = Xu[r + 2080 + kc + 4];
#pragma unroll
        for (int j = 0; j < 2; j++) {
            int nt = nh * 2 + j;
            uint2 bb = __ldg(((const uint2*)g_LDf) + (ks * 4 + nt) * 32 + lane);
            mma_tf32(acc[j], a0, a1, a2, a3, bb.x, bb.y);
        }
    }
#pragma unroll
    for (int j = 0; j < 2; j++) {
        int col = nh * 16 + j * 8 + 2 * t;
        int row0 = nb + mf * 16 + g;
        if (row0 < N_NODES)
            *(float2*)&g_xld[(size_t)row0 * 32 + col] = make_float2(acc[j].x, acc[j].y);
        if (row0 + 8 < N_NODES)
            *(float2*)&g_xld[(size_t)(row0 + 8) * 32 + col] = make_float2(acc[j].z, acc[j].w);
    }
}

// ---------------------------------------------------------------------------
// Edge kernel: 32 edges per block
// ---------------------------------------------------------------------------
__global__ __launch_bounds__(256) void edge_kernel(
    const float* __restrict__ x,
    const int*   __restrict__ edge_idx,
    const int*   __restrict__ edge_attr,
    const float* __restrict__ node_elec,
    const float* __restrict__ emb_edge,
    const float* __restrict__ moa_w,
    const float* __restrict__ moa_s,
    const float* __restrict__ elec_lin)
{
    __shared__ int   s_i0[32], s_i1[32];
    __shared__ float emb_s[32][33];

    const int tid = threadIdx.x;
    const int eb  = blockIdx.x * 32;

    if (tid < 32) {
        int i0 = edge_idx[eb + tid];
        int i1 = edge_idx[N_EDGES + eb + tid];
        s_i0[tid] = i0;
        s_i1[tid] = i1;
        atomicAdd(&g_indeg[i1], 1);
    }
    __syncthreads();

    {
        const int wid = tid >> 5, lane = tid & 31;
        float w0 = sp(moa_w[lane]);
        float w1 = sp(moa_w[32 + lane]);
        w0 /= wsum(w0);
        w1 /= wsum(w1);
        const float s0  = sp(moa_s[lane]);
        const float s1  = sp(moa_s[32 + lane]);
        const float el0 = elec_lin[lane];
        const float el1 = elec_lin[32 + lane];
#pragma unroll
        for (int i = 0; i < 4; i++) {
            int e  = wid * 4 + i;
            int i0 = s_i0[e], i1 = s_i1[e];
            float d0 = node_elec[2 * i0]     - node_elec[2 * i1];
            float d1 = node_elec[2 * i0 + 1] - node_elec[2 * i1 + 1];
            float m0 = wsum(tanhf(d0 * s0) * w0);
            float m1 = wsum(tanhf(d1 * s1) * w1);
            int ge = eb + e;
            int a0 = edge_attr[3 * ge], a1 = edge_attr[3 * ge + 1], a2 = edge_attr[3 * ge + 2];
            emb_s[e][lane] = emb_edge[a0 * 32 + lane] + emb_edge[a1 * 32 + lane] +
                             emb_edge[a2 * 32 + lane] + m0 * el0 + m1 * el1;
        }
    }
    __syncthreads();

    const int e  = tid >> 3;
    const int i0 = s_i0[e], i1 = s_i1[e];

    {
        const int d = (tid & 7) * 4;
        float4 a = __ldg((const float4*)(g_xld + (size_t)i0 * 32 + d));
        float4 b = __ldg((const float4*)(g_xld + (size_t)i1 * 32 + d));
        float4 t;
        t.x = (a.x + b.x) * emb_s[e][d + 0];
        t.y = (a.y + b.y) * emb_s[e][d + 1];
        t.z = (a.z + b.z) * emb_s[e][d + 2];
        t.w = (a.w + b.w) * emb_s[e][d + 3];
        red_add_v4(g_t2 + (size_t)i1 * 32 + d, t);
    }
    {
        const int c0 = (tid & 7) * 4;
        const float4* xr = (const float4*)(x + (size_t)i0 * WIDTH);
        float* dst = g_aggx + (size_t)i1 * WIDTH;
#pragma unroll
        for (int it = 0; it < 8; it++) {
            int c = c0 + it * 32;
            float4 v = __ldg(&xr[c >> 2]);
            red_add_v4(dst + c, v);
        }
    }
}

// ---------------------------------------------------------------------------
// Node kernel: 32 nodes per block, 256 threads (8 warps), 2 blocks/SM.
// smem: A_s[32][292] ; u_s[32][260] ; v_s[32][260] ; avv = 2x[32][132] in A_s
// ---------------------------------------------------------------------------
__global__ __launch_bounds__(256) void node_kernel(
    const float* __restrict__ x,
    const int*   __restrict__ deg,
    const float* __restrict__ emb_deg,
    const float* __restrict__ act_bias,
    float*       __restrict__ out)
{
    extern __shared__ float sm[];
    float* A_s   = sm;                    // [32][292] = 9344 floats
    float* u_s   = sm + 32 * 292;         // [32][260]
    float* v_s   = u_s + 32 * 260;        // [32][260]
    float* avv_s = A_s;                   // 2 x [32][132] = 8448 floats (fits)

    const int tid  = threadIdx.x;
    const int nb   = blockIdx.x * MTILE;
    const int lane = tid & 31, wid = tid >> 5;
    const int g = lane >> 2, t = lane & 3;

    // --- stage inputs (tf32-rounded): raw agg | t2 ---
    {
        const int n  = tid >> 3;
        const int c0 = (tid & 7) * 4;
        const int gcl = min(nb + n, N_NODES - 1);
        const float idg = (float)__ldg(&g_indeg[gcl]);
        const float* ra = g_aggx + (size_t)gcl * WIDTH;
        const float* rx = x + (size_t)gcl * WIDTH;
#pragma unroll
        for (int it = 0; it < 8; it++) {
            int c = c0 + it * 32;
            float4 a  = *(const float4*)(ra + c);
            float4 xv = __ldg((const float4*)(rx + c));
            A_s[n * 292 + c + 0] = tf32r(a.x + idg * xv.x);
            A_s[n * 292 + c + 1] = tf32r(a.y + idg * xv.y);
            A_s[n * 292 + c + 2] = tf32r(a.z + idg * xv.z);
            A_s[n * 292 + c + 3] = tf32r(a.w + idg * xv.w);
        }
        // t2: 32 rows x 32 cols = 256 float4 tasks / 8 per row
        float4 t2v = *(const float4*)(g_t2 + (size_t)gcl * 32 + c0);
        A_s[n * 292 + 256 + c0 + 0] = tf32r(t2v.x);
        A_s[n * 292 + 256 + c0 + 1] = tf32r(t2v.y);
        A_s[n * 292 + 256 + c0 + 2] = tf32r(t2v.z);
        A_s[n * 292 + 256 + c0 + 3] = tf32r(t2v.w);
    }
    __syncthreads();

    // --- Stage A: [32x288] @ W2[288x512] -> U|V  (8 warps: 8 N-splits) ---
    {
        const int wn = wid;                // 0..7, 64 cols each
        const unsigned* Au = (const unsigned*)A_s;
        float4 acc[2][8];
#pragma unroll
        for (int mf = 0; mf < 2; mf++)
#pragma unroll
            for (int nt = 0; nt < 8; nt++)
                acc[mf][nt] = make_float4(0.f, 0.f, 0.f, 0.f);

        const uint2* Bp = ((const uint2*)g_W2f) + (wn * 8) * 32 + lane;
#pragma unroll 4
        for (int ks = 0; ks < 36; ks++) {
            int kc = ks * 8 + t;
            unsigned a0[2], a1[2], a2[2], a3[2];
#pragma unroll
            for (int mf = 0; mf < 2; mf++) {
                int r = (mf * 16 + g) * 292;
                a0[mf] = Au[r + kc];
                a1[mf] = Au[r + 2336 + kc];        // +8 rows (8*292)
                a2[mf] = Au[r + kc + 4];
                a3[mf] = Au[r + 2336 + kc + 4];
            }
            const uint2* Bks = Bp + ks * 64 * 32;
#pragma unroll
            for (int nt = 0; nt < 8; nt++) {
                uint2 bb = __ldg(Bks + nt * 32);
#pragma unroll
                for (int mf = 0; mf < 2; mf++)
                    mma_tf32(acc[mf][nt], a0[mf], a1[mf], a2[mf], a3[mf], bb.x, bb.y);
            }
        }
        float* dst = (wn < 4) ? u_s : v_s;
        const int cb = (wn & 3) * 64;
#pragma unroll
        for (int mf = 0; mf < 2; mf++)
#pragma unroll
            for (int nt = 0; nt < 8; nt++) {
                int c = cb + nt * 8 + 2 * t;
                int r = (mf * 16 + g) * 260;
                *(float2*)&dst[r + c]        = make_float2(acc[mf][nt].x, acc[mf][nt].y);
                *(float2*)&dst[r + 2080 + c] = make_float2(acc[mf][nt].z, acc[mf][nt].w);
            }
    }
    __syncthreads();

    // --- per-(node,head) RMS norm; one task per thread (32x8 = 256) ---
    {
        const int n = tid & 31, h = tid >> 5;
        const int gcl = min(nb + n, N_NODES - 1);
        const int dd = __ldg(&deg[gcl]);
        const float inv_s2 = 0.70710678118654752440f;

        float4 uu[8];
        float ss = 0.f;
#pragma unroll
        for (int i = 0; i < 8; i++) {
            uu[i] = *(float4*)&u_s[n * 260 + h * 32 + 4 * i];
            ss += uu[i].x * uu[i].x + uu[i].y * uu[i].y +
                  uu[i].z * uu[i].z + uu[i].w * uu[i].w;
        }
        float rinv = rsqrtf(ss * (1.f / 32.f) + 1e-6f);
#pragma unroll
        for (int i = 0; i < 8; i++) {
            float4 b = __ldg((const float4*)(emb_deg + dd * 256 + h * 32 + 4 * i));
            u_s[n * 260 + h * 32 + 4 * i + 0] = tf32r((uu[i].x * rinv + b.x) * inv_s2);
            u_s[n * 260 + h * 32 + 4 * i + 1] = tf32r((uu[i].y * rinv + b.y) * inv_s2);
            u_s[n * 260 + h * 32 + 4 * i + 2] = tf32r((uu[i].z * rinv + b.z) * inv_s2);
            u_s[n * 260 + h * 32 + 4 * i + 3] = tf32r((uu[i].w * rinv + b.w) * inv_s2);
        }
        float4 vv4[8];
        float ssv = 0.f;
#pragma unroll
        for (int i = 0; i < 8; i++) {
            vv4[i] = *(float4*)&v_s[n * 260 + h * 32 + 4 * i];
            ssv += vv4[i].x * vv4[i].x + vv4[i].y * vv4[i].y +
                   vv4[i].z * vv4[i].z + vv4[i].w * vv4[i].w;
        }
        float rinvv = rsqrtf(ssv * (1.f / 32.f) + 1e-6f);
#pragma unroll
        for (int i = 0; i < 8; i++) {
            v_s[n * 260 + h * 32 + 4 * i + 0] = tf32r(vv4[i].x * rinvv);
            v_s[n * 260 + h * 32 + 4 * i + 1] = tf32r(vv4[i].y * rinvv);
            v_s[n * 260 + h * 32 + 4 * i + 2] = tf32r(vv4[i].z * rinvv);
            v_s[n * 260 + h * 32 + 4 * i + 3] = tf32r(vv4[i].w * rinvv);
        }
    }
    __syncthreads();

    const float CLIP_LO = 0.22360679774997896f;
    const float CLIP_HI = 4.47213595499957939f;
    const unsigned* U32 = (const unsigned*)u_s;
    const unsigned* V32 = (const unsigned*)v_s;

#pragma unroll 1
    for (int hp = 0; hp < 4; hp++) {
        // --- Stage B: 8 warps = 2 heads x 4 Nquarter ---
        {
            const int sub = wid >> 2;            // head in pair
            const int nq  = wid & 3;             // 32-col quarter of 128
            const int h   = hp * 2 + sub;
            float* avv = avv_s + sub * (32 * 132);

            float4 ag[2][4], av4[2][4];
#pragma unroll
            for (int mf = 0; mf < 2; mf++)
#pragma unroll
                for (int j = 0; j < 4; j++) {
                    ag[mf][j]  = make_float4(0.f, 0.f, 0.f, 0.f);
                    av4[mf][j] = make_float4(0.f, 0.f, 0.f, 0.f);
                }
#pragma unroll
            for (int ks = 0; ks < 4; ks++) {
                int col = h * 32 + ks * 8 + t;
                unsigned ua0[2], ua1[2], ua2[2], ua3[2];
                unsigned va0[2], va1[2], va2[2], va3[2];
#pragma unroll
                for (int mf = 0; mf < 2; mf++) {
                    int r = (mf * 16 + g) * 260;
                    ua0[mf] = U32[r + col];        ua1[mf] = U32[r + 2080 + col];
                    ua2[mf] = U32[r + col + 4];    ua3[mf] = U32[r + 2080 + col + 4];
                    va0[mf] = V32[r + col];        va1[mf] = V32[r + 2080 + col];
                    va2[mf] = V32[r + col + 4];    va3[mf] = V32[r + 2080 + col + 4];
                }
#pragma unroll
                for (int j = 0; j < 4; j++) {
                    int nt16 = nq * 4 + j;
                    uint2 bg = __ldg(((const uint2*)g_GVf) +
                                     ((h * 4 + ks) * 16 + nt16) * 32 + lane);
                    uint2 bv = __ldg(((const uint2*)g_GVf) +
                                     (((8 + h) * 4 + ks) * 16 + nt16) * 32 + lane);
#pragma unroll
                    for (int mf = 0; mf < 2; mf++) {
                        mma_tf32(ag[mf][j],  ua0[mf], ua1[mf], ua2[mf], ua3[mf], bg.x, bg.y);
                        mma_tf32(av4[mf][j], va0[mf], va1[mf], va2[mf], va3[mf], bv.x, bv.y);
                    }
                }
            }
#pragma unroll
            for (int j = 0; j < 4; j++) {
                int c = nq * 32 + j * 8 + 2 * t;
                float2 bias = __ldg((const float2*)(act_bias + h * 128 + c));
#pragma unroll
                for (int mf = 0; mf < 2; mf++) {
                    int r = (mf * 16 + g) * 132;
                    float o0 = fminf(fmaxf(sp(ag[mf][j].x + bias.x), CLIP_LO), CLIP_HI) * av4[mf][j].x;
                    float o1 = fminf(fmaxf(sp(ag[mf][j].y + bias.y), CLIP_LO), CLIP_HI) * av4[mf][j].y;
                    float o2 = fminf(fmaxf(sp(ag[mf][j].z + bias.x), CLIP_LO), CLIP_HI) * av4[mf][j].z;
                    float o3 = fminf(fmaxf(sp(ag[mf][j].w + bias.y), CLIP_LO), CLIP_HI) * av4[mf][j].w;
                    avv[r + c + 0]        = tf32r(o0);
                    avv[r + c + 1]        = tf32r(o1);
                    avv[r + 1056 + c + 0] = tf32r(o2);
                    avv[r + 1056 + c + 1] = tf32r(o3);
                }
            }
        }
        __syncthreads();

        // --- Stage D: 8 warps = 2 heads x 4 col8 ---
        {
            const int sub = wid >> 2;
            const int c8  = wid & 3;
            const int h   = hp * 2 + sub;
            const unsigned* AV = (const unsigned*)(avv_s + sub * (32 * 132));
            float4 dacc[2];
#pragma unroll
            for (int mf = 0; mf < 2; mf++) dacc[mf] = make_float4(0.f, 0.f, 0.f, 0.f);
#pragma unroll
            for (int ks = 0; ks < 16; ks++) {
                int kc = ks * 8 + t;
                uint2 bb = __ldg(((const uint2*)g_Pf) +
                                 ((h * 16 + ks) * 4 + c8) * 32 + lane);
#pragma unroll
                for (int mf = 0; mf < 2; mf++) {
                    int r = (mf * 16 + g) * 132;
                    mma_tf32(dacc[mf], AV[r + kc], AV[r + 1056 + kc],
                             AV[r + kc + 4], AV[r + 1056 + kc + 4], bb.x, bb.y);
                }
            }
            int col = h * 32 + c8 * 8 + 2 * t;
#pragma unroll
            for (int mf = 0; mf < 2; mf++) {
                int row0 = nb + mf * 16 + g;
                if (row0 < N_NODES)
                    *(float2*)&out[(size_t)row0 * WIDTH + col] =
                        make_float2(dacc[mf].x, dacc[mf].y);
                if (row0 + 8 < N_NODES)
                    *(float2*)&out[(size_t)(row0 + 8) * WIDTH + col] =
                        make_float2(dacc[mf].z, dacc[mf].w);
            }
        }
        __syncthreads();
    }
}

// ---------------------------------------------------------------------------
// Launch
// ---------------------------------------------------------------------------
extern "C" void kernel_launch(void* const* d_in, const int* in_sizes, int n_in,
                              void* d_out, int out_size) {
    const float* x            = (const float*)d_in[0];
    const int*   deg          = (const int*)  d_in[1];
    const int*   edge_idx     = (const int*)  d_in[2];
    const int*   edge_attr    = (const int*)  d_in[3];
    const float* node_elec    = (const float*)d_in[4];
    const float* lora_down    = (const float*)d_in[5];
    const float* lora_up      = (const float*)d_in[6];
    const float* emb_edge     = (const float*)d_in[7];
    const float* moa_w        = (const float*)d_in[8];
    const float* moa_s        = (const float*)d_in[9];
    const float* elec_lin     = (const float*)d_in[10];
    const float* emb_deg      = (const float*)d_in[11];
    const float* lin_pre      = (const float*)d_in[12];
    const float* gate_lin     = (const float*)d_in[13];
    const float* gate_kernel  = (const float*)d_in[14];
    const float* value_lin    = (const float*)d_in[15];
    const float* value_kernel = (const float*)d_in[16];
    const float* act_bias     = (const float*)d_in[17];
    const float* post_kernel  = (const float*)d_in[18];
    float* out = (float*)d_out;

    prep_kernel<<<1584, 256>>>(lin_pre, lora_up, gate_lin, value_lin,
                               gate_kernel, value_kernel, post_kernel, lora_down);

    size_t xsm = (size_t)64 * 260 * sizeof(float);       // 66560 B
    cudaFuncSetAttribute(xld_kernel,
                         cudaFuncAttributeMaxDynamicSharedMemorySize, (int)xsm);
    xld_kernel<<<(N_NODES + 63) / 64, 256, xsm>>>(x);

    edge_kernel<<<N_EDGES / 32, 256>>>(
        x, edge_idx, edge_attr, node_elec,
        emb_edge, moa_w, moa_s, elec_lin);

    size_t nsm = ((size_t)32 * 292 + 2 * 32 * 260) * sizeof(float);  // 103936 B
    cudaFuncSetAttribute(node_kernel,
                         cudaFuncAttributeMaxDynamicSharedMemorySize, (int)nsm);
    node_kernel<<<(N_NODES + MTILE - 1) / MTILE, 256, nsm>>>(
        x, deg, emb_deg, act_bias, out);
}

// round 9
// speedup vs baseline: 5.5351x; 1.0133x over previous
#include <cuda_runtime.h>
#include <cstddef>

#define N_NODES   60000
#define N_EDGES   240000
#define WIDTH     256
#define DIM_HEAD  32
#define NUM_HEAD  8
#define MTILE     32

// ---------------------------------------------------------------------------
// Device scratch
// ---------------------------------------------------------------------------
__device__ float g_aggx[(size_t)N_NODES * WIDTH];     // segment_sum(x[i0])
__device__ float g_t2  [(size_t)N_NODES * DIM_HEAD];  // segment_sum(t2)
__device__ int   g_indeg[N_NODES];
__device__ float g_xld [(size_t)N_NODES * DIM_HEAD];  // x @ lora_down

// mma-B-fragment swizzled weights (tf32-rounded fp32 bit patterns)
__device__ float g_W2f[36 * 64 * 32 * 2];          // W2 288x512: [ks][col8][lane][2]
__device__ float g_GVf[2 * 8 * 4 * 16 * 32 * 2];   // gate/value kernels
__device__ float g_Pf [8 * 16 * 4 * 32 * 2];       // post kernel

__device__ __forceinline__ float sp(float x) {
    return fmaxf(x, 0.f) + log1pf(expf(-fabsf(x)));
}
__device__ __forceinline__ float wsum(float v) {
#pragma unroll
    for (int o = 16; o; o >>= 1) v += __shfl_xor_sync(0xffffffffu, v, o);
    return v;
}
__device__ __forceinline__ void red_add_v4(float* p, float4 v) {
    asm volatile("red.global.add.v4.f32 [%0], {%1, %2, %3, %4};"
                 :: "l"(p), "f"(v.x), "f"(v.y), "f"(v.z), "f"(v.w)
                 : "memory");
}
__device__ __forceinline__ float tf32r(float f) {
    unsigned r;
    asm("cvt.rna.tf32.f32 %0, %1;" : "=r"(r) : "f"(f));
    return __uint_as_float(r);
}
__device__ __forceinline__ void mma_tf32(float4& c,
    unsigned a0, unsigned a1, unsigned a2, unsigned a3,
    unsigned b0, unsigned b1)
{
    asm volatile(
        "mma.sync.aligned.m16n8k8.row.col.f32.tf32.tf32.f32 "
        "{%0,%1,%2,%3},{%4,%5,%6,%7},{%8,%9},{%0,%1,%2,%3};"
        : "+f"(c.x), "+f"(c.y), "+f"(c.z), "+f"(c.w)
        : "r"(a0), "r"(a1), "r"(a2), "r"(a3), "r"(b0), "r"(b1));
}

// ---------------------------------------------------------------------------
// init_kernel: blocks [0,1875) xld via mma (lora_down read directly in
// fragment order); blocks [1875,2899) zero g_aggx/g_t2/g_indeg.
// ---------------------------------------------------------------------------
__global__ __launch_bounds__(256) void init_kernel(
    const float* __restrict__ x,
    const float* __restrict__ lora_down)
{
    const int b = blockIdx.x, tid = threadIdx.x;
    if (b < 1875) {
        extern __shared__ float xs[];      // [32][260]
        const int nb = b * 32;
        const int lane = tid & 31, wid = tid >> 5;
        const int g = lane >> 2, t = lane & 3;
        {
            const int n  = tid >> 3;
            const int c0 = (tid & 7) * 4;
            const int gcl = min(nb + n, N_NODES - 1);
            const float* xr = x + (size_t)gcl * WIDTH;
#pragma unroll
            for (int it = 0; it < 8; it++) {
                int c = c0 + it * 32;
                float4 v = __ldg((const float4*)(xr + c));
                xs[n * 260 + c + 0] = tf32r(v.x);
                xs[n * 260 + c + 1] = tf32r(v.y);
                xs[n * 260 + c + 2] = tf32r(v.z);
                xs[n * 260 + c + 3] = tf32r(v.w);
            }
        }
        __syncthreads();
        const int wm = wid >> 2, wn = wid & 3;   // 2 M x 4 N
        const unsigned* Xu = (const unsigned*)xs;
        const int r = (wm * 16 + g) * 260;
        float4 acc = make_float4(0.f, 0.f, 0.f, 0.f);
#pragma unroll 4
        for (int ks = 0; ks < 32; ks++) {
            int kc = ks * 8 + t;
            unsigned a0 = Xu[r + kc];
            unsigned a1 = Xu[r + 2080 + kc];
            unsigned a2 = Xu[r + kc + 4];
            unsigned a3 = Xu[r + 2080 + kc + 4];
            unsigned b0 = __float_as_uint(
                tf32r(__ldg(&lora_down[(ks * 8 + t) * 32 + wn * 8 + g])));
            unsigned b1 = __float_as_uint(
                tf32r(__ldg(&lora_down[(ks * 8 + 4 + t) * 32 + wn * 8 + g])));
            mma_tf32(acc, a0, a1, a2, a3, b0, b1);
        }
        int col = wn * 8 + 2 * t;
        int row0 = nb + wm * 16 + g;
        if (row0 < N_NODES)
            *(float2*)&g_xld[(size_t)row0 * 32 + col] = make_float2(acc.x, acc.y);
        if (row0 + 8 < N_NODES)
            *(float2*)&g_xld[(size_t)(row0 + 8) * 32 + col] = make_float2(acc.z, acc.w);
    } else {
        size_t i0 = (size_t)(b - 1875) * 256 + tid;
        size_t step = (size_t)1024 * 256;
        size_t n4 = (size_t)N_NODES * WIDTH / 4;
        float4* p = (float4*)g_aggx;
        for (size_t i = i0; i < n4; i += step)
            p[i] = make_float4(0.f, 0.f, 0.f, 0.f);
        size_t m4 = (size_t)N_NODES * DIM_HEAD / 4;
        float4* q4 = (float4*)g_t2;
        for (size_t i = i0; i < m4; i += step)
            q4[i] = make_float4(0.f, 0.f, 0.f, 0.f);
        for (size_t i = i0; i < N_NODES; i += step)
            g_indeg[i] = 0;
    }
}

// ---------------------------------------------------------------------------
// work_kernel: blocks [0,7500) edge ; [7500,7644) W2 gemm+swizzle ;
// [7644,7900) gate/value swizzle ; [7900,8028) post swizzle.
// ---------------------------------------------------------------------------
__global__ __launch_bounds__(256) void work_kernel(
    const float* __restrict__ x,
    const int*   __restrict__ edge_idx,
    const int*   __restrict__ edge_attr,
    const float* __restrict__ node_elec,
    const float* __restrict__ emb_edge,
    const float* __restrict__ moa_w,
    const float* __restrict__ moa_s,
    const float* __restrict__ elec_lin,
    const float* __restrict__ lin_pre,
    const float* __restrict__ lora_up,
    const float* __restrict__ gate_lin,
    const float* __restrict__ value_lin,
    const float* __restrict__ gate_kernel,
    const float* __restrict__ value_kernel,
    const float* __restrict__ post_kernel)
{
    __shared__ int   s_i0[32], s_i1[32];
    __shared__ float emb_s[32][33];

    const int b = blockIdx.x, tid = threadIdx.x;

    if (b < 7500) {
        const int eb = b * 32;
        if (tid < 32) {
            int i0 = edge_idx[eb + tid];
            int i1 = edge_idx[N_EDGES + eb + tid];
            s_i0[tid] = i0;
            s_i1[tid] = i1;
            atomicAdd(&g_indeg[i1], 1);
        }
        __syncthreads();
        {
            const int wid = tid >> 5, lane = tid & 31;
            float w0 = sp(moa_w[lane]);
            float w1 = sp(moa_w[32 + lane]);
            w0 /= wsum(w0);
            w1 /= wsum(w1);
            const float s0  = sp(moa_s[lane]);
            const float s1  = sp(moa_s[32 + lane]);
            const float el0 = elec_lin[lane];
            const float el1 = elec_lin[32 + lane];
#pragma unroll
            for (int i = 0; i < 4; i++) {
                int e  = wid * 4 + i;
                int i0 = s_i0[e], i1 = s_i1[e];
                float d0 = node_elec[2 * i0]     - node_elec[2 * i1];
                float d1 = node_elec[2 * i0 + 1] - node_elec[2 * i1 + 1];
                float m0 = wsum(tanhf(d0 * s0) * w0);
                float m1 = wsum(tanhf(d1 * s1) * w1);
                int ge = eb + e;
                int a0 = edge_attr[3 * ge], a1 = edge_attr[3 * ge + 1],
                    a2 = edge_attr[3 * ge + 2];
                emb_s[e][lane] = emb_edge[a0 * 32 + lane] + emb_edge[a1 * 32 + lane] +
                                 emb_edge[a2 * 32 + lane] + m0 * el0 + m1 * el1;
            }
        }
        __syncthreads();

        const int e  = tid >> 3;
        const int i0 = s_i0[e], i1 = s_i1[e];
        {
            const int d = (tid & 7) * 4;
            float4 a = __ldg((const float4*)(g_xld + (size_t)i0 * 32 + d));
            float4 bb = __ldg((const float4*)(g_xld + (size_t)i1 * 32 + d));
            float4 t;
            t.x = (a.x + bb.x) * emb_s[e][d + 0];
            t.y = (a.y + bb.y) * emb_s[e][d + 1];
            t.z = (a.z + bb.z) * emb_s[e][d + 2];
            t.w = (a.w + bb.w) * emb_s[e][d + 3];
            red_add_v4(g_t2 + (size_t)i1 * 32 + d, t);
        }
        {
            const int c0 = (tid & 7) * 4;
            const float4* xr = (const float4*)(x + (size_t)i0 * WIDTH);
            float* dst = g_aggx + (size_t)i1 * WIDTH;
#pragma unroll
            for (int it = 0; it < 8; it++) {
                int c = c0 + it * 32;
                float4 v = __ldg(&xr[c >> 2]);
                red_add_v4(dst + c, v);
            }
        }
    } else if (b < 7644) {
        int id = (b - 7500) * 256 + tid;   // 36864
        int k  = id >> 7;                  // 0..287
        int n  = (id & 127) * 4;           // 0..508
        const float* srow = (k < 256) ? (lin_pre + k * 256)
                                      : (lora_up + (k - 256) * 256);
        const float* M = (n < 256) ? gate_lin : value_lin;
        int nn = n & 255;
        float4 acc = make_float4(0.f, 0.f, 0.f, 0.f);
#pragma unroll 4
        for (int j = 0; j < 256; j++) {
            float  s = __ldg(&srow[j]);
            float4 m = __ldg((const float4*)(M + j * 256 + nn));
            acc.x += s * m.x; acc.y += s * m.y;
            acc.z += s * m.z; acc.w += s * m.w;
        }
        int ks = k >> 3, kin = k & 7, tig = kin & 3, jj = kin >> 2;
        float v[4] = {acc.x, acc.y, acc.z, acc.w};
#pragma unroll
        for (int q = 0; q < 4; q++) {
            int nq = n + q;
            int idx = ((ks * 64 + (nq >> 3)) * 32 + ((nq & 7) * 4 + tig)) * 2 + jj;
            g_W2f[idx] = tf32r(v[q]);
        }
    } else if (b < 7900) {
        int id = (b - 7644) * 256 + tid;   // 65536
        int path = id >> 15;
        int h    = (id >> 12) & 7;
        int d    = (id >> 7) & 31;
        int f    = id & 127;
        float val = path ? __ldg(&value_kernel[h * 4096 + d * 128 + f])
                         : __ldg(&gate_kernel [h * 4096 + d * 128 + f]);
        int ks = d >> 3, kin = d & 7, tig = kin & 3, jj = kin >> 2;
        int nt = f >> 3, g = f & 7;
        int idx = (((((path * 8 + h) * 4 + ks) * 16 + nt) * 32) + (g * 4 + tig)) * 2 + jj;
        g_GVf[idx] = tf32r(val);
    } else {
        int p = (b - 7900) * 256 + tid;    // 32768
        int h = p >> 12;
        int f = (p >> 5) & 127;
        int d2 = p & 31;
        float val = __ldg(&post_kernel[h * 4096 + f * 32 + d2]);
        int ks = f >> 3, kin = f & 7, tig = kin & 3, jj = kin >> 2;
        int nt = d2 >> 3, g = d2 & 7;
        int idx = ((((h * 16 + ks) * 4 + nt) * 32) + (g * 4 + tig)) * 2 + jj;
        g_Pf[idx] = tf32r(val);
    }
}

// ---------------------------------------------------------------------------
// Node kernel: 32 nodes per block, 256 threads, 2 blocks/SM.
// Stage A fuses the per-(row,head) RMS norm into its epilogue via shfl.
// smem: A_s[32][292] ; u_s[32][260] ; v_s[32][260] ; avv = 2x[32][132] in A_s
// ---------------------------------------------------------------------------
__global__ __launch_bounds__(256) void node_kernel(
    const float* __restrict__ x,
    const int*   __restrict__ deg,
    const float* __restrict__ emb_deg,
    const float* __restrict__ act_bias,
    float*       __restrict__ out)
{
    extern __shared__ float sm[];
    float* A_s   = sm;                    // [32][292]
    float* u_s   = sm + 32 * 292;         // [32][260]
    float* v_s   = u_s + 32 * 260;        // [32][260]
    float* avv_s = A_s;                   // 2 x [32][132]

    const int tid  = threadIdx.x;
    const int nb   = blockIdx.x * MTILE;
    const int lane = tid & 31, wid = tid >> 5;
    const int g = lane >> 2, t = lane & 3;

    // --- stage inputs (tf32-rounded): raw agg | t2 ---
    {
        const int n  = tid >> 3;
        const int c0 = (tid & 7) * 4;
        const int gcl = min(nb + n, N_NODES - 1);
        const float idg = (float)__ldg(&g_indeg[gcl]);
        const float* ra = g_aggx + (size_t)gcl * WIDTH;
        const float* rx = x + (size_t)gcl * WIDTH;
#pragma unroll
        for (int it = 0; it < 8; it++) {
            int c = c0 + it * 32;
            float4 a  = *(const float4*)(ra + c);
            float4 xv = __ldg((const float4*)(rx + c));
            A_s[n * 292 + c + 0] = tf32r(a.x + idg * xv.x);
            A_s[n * 292 + c + 1] = tf32r(a.y + idg * xv.y);
            A_s[n * 292 + c + 2] = tf32r(a.z + idg * xv.z);
            A_s[n * 292 + c + 3] = tf32r(a.w + idg * xv.w);
        }
        float4 t2v = *(const float4*)(g_t2 + (size_t)gcl * 32 + c0);
        A_s[n * 292 + 256 + c0 + 0] = tf32r(t2v.x);
        A_s[n * 292 + 256 + c0 + 1] = tf32r(t2v.y);
        A_s[n * 292 + 256 + c0 + 2] = tf32r(t2v.z);
        A_s[n * 292 + 256 + c0 + 3] = tf32r(t2v.w);
    }
    __syncthreads();

    // --- Stage A: [32x288] @ W2[288x512] -> U|V with fused RMS norm ---
    {
        const int wn = wid;                // 0..7, 64 cols each
        const unsigned* Au = (const unsigned*)A_s;
        float4 acc[2][8];
#pragma unroll
        for (int mf = 0; mf < 2; mf++)
#pragma unroll
            for (int nt = 0; nt < 8; nt++)
                acc[mf][nt] = make_float4(0.f, 0.f, 0.f, 0.f);

        const uint2* Bp = ((const uint2*)g_W2f) + (wn * 8) * 32 + lane;
#pragma unroll 4
        for (int ks = 0; ks < 36; ks++) {
            int kc = ks * 8 + t;
            unsigned a0[2], a1[2], a2[2], a3[2];
#pragma unroll
            for (int mf = 0; mf < 2; mf++) {
                int r = (mf * 16 + g) * 292;
                a0[mf] = Au[r + kc];
                a1[mf] = Au[r + 2336 + kc];        // +8 rows
                a2[mf] = Au[r + kc + 4];
                a3[mf] = Au[r + 2336 + kc + 4];
            }
            const uint2* Bks = Bp + ks * 64 * 32;
#pragma unroll
            for (int nt = 0; nt < 8; nt++) {
                uint2 bb = __ldg(Bks + nt * 32);
#pragma unroll
                for (int mf = 0; mf < 2; mf++)
                    mma_tf32(acc[mf][nt], a0[mf], a1[mf], a2[mf], a3[mf], bb.x, bb.y);
            }
        }

        // fused RMS epilogue: cols of one head live in lanes g*4+{0..3}
        const bool isU = (wn < 4);
        float* dst = isU ? u_s : v_s;
        const int cb = (wn & 3) * 64;
        const float inv_s2 = 0.70710678118654752440f;
#pragma unroll
        for (int mf = 0; mf < 2; mf++) {
            const int rA = mf * 16 + g;
            const int rB = rA + 8;
            int dgA = 0, dgB = 0;
            if (isU) {
                dgA = __ldg(&deg[min(nb + rA, N_NODES - 1)]) * 256;
                dgB = __ldg(&deg[min(nb + rB, N_NODES - 1)]) * 256;
            }
#pragma unroll
            for (int hh = 0; hh < 2; hh++) {
                float sA = 0.f, sB = 0.f;
#pragma unroll
                for (int j = 0; j < 4; j++) {
                    float4 a = acc[mf][hh * 4 + j];
                    sA += a.x * a.x + a.y * a.y;
                    sB += a.z * a.z + a.w * a.w;
                }
                sA += __shfl_xor_sync(0xffffffffu, sA, 1);
                sA += __shfl_xor_sync(0xffffffffu, sA, 2);
                sB += __shfl_xor_sync(0xffffffffu, sB, 1);
                sB += __shfl_xor_sync(0xffffffffu, sB, 2);
                float rinvA = rsqrtf(sA * (1.f / 32.f) + 1e-6f);
                float rinvB = rsqrtf(sB * (1.f / 32.f) + 1e-6f);
#pragma unroll
                for (int j = 0; j < 4; j++) {
                    float4 a = acc[mf][hh * 4 + j];
                    int c = cb + (hh * 4 + j) * 8 + 2 * t;
                    if (isU) {
                        float2 bA = __ldg((const float2*)(emb_deg + dgA + c));
                        float2 bB = __ldg((const float2*)(emb_deg + dgB + c));
                        *(float2*)&dst[rA * 260 + c] = make_float2(
                            tf32r((a.x * rinvA + bA.x) * inv_s2),
                            tf32r((a.y * rinvA + bA.y) * inv_s2));
                        *(float2*)&dst[rB * 260 + c] = make_float2(
                            tf32r((a.z * rinvB + bB.x) * inv_s2),
                            tf32r((a.w * rinvB + bB.y) * inv_s2));
                    } else {
                        *(float2*)&dst[rA * 260 + c] = make_float2(
                            tf32r(a.x * rinvA), tf32r(a.y * rinvA));
                        *(float2*)&dst[rB * 260 + c] = make_float2(
                            tf32r(a.z * rinvB), tf32r(a.w * rinvB));
                    }
                }
            }
        }
    }
    __syncthreads();

    const float CLIP_LO = 0.22360679774997896f;
    const float CLIP_HI = 4.47213595499957939f;
    const unsigned* U32 = (const unsigned*)u_s;
    const unsigned* V32 = (const unsigned*)v_s;

#pragma unroll 1
    for (int hp = 0; hp < 4; hp++) {
        // --- Stage B: 8 warps = 2 heads x 4 Nquarter ---
        {
            const int sub = wid >> 2;
            const int nq  = wid & 3;
            const int h   = hp * 2 + sub;
            float* avv = avv_s + sub * (32 * 132);

            float4 ag[2][4], av4[2][4];
#pragma unroll
            for (int mf = 0; mf < 2; mf++)
#pragma unroll
                for (int j = 0; j < 4; j++) {
                    ag[mf][j]  = make_float4(0.f, 0.f, 0.f, 0.f);
                    av4[mf][j] = make_float4(0.f, 0.f, 0.f, 0.f);
                }
#pragma unroll
            for (int ks = 0; ks < 4; ks++) {
                int col = h * 32 + ks * 8 + t;
                unsigned ua0[2], ua1[2], ua2[2], ua3[2];
                unsigned va0[2], va1[2], va2[2], va3[2];
#pragma unroll
                for (int mf = 0; mf < 2; mf++) {
                    int r = (mf * 16 + g) * 260;
                    ua0[mf] = U32[r + col];        ua1[mf] = U32[r + 2080 + col];
                    ua2[mf] = U32[r + col + 4];    ua3[mf] = U32[r + 2080 + col + 4];
                    va0[mf] = V32[r + col];        va1[mf] = V32[r + 2080 + col];
                    va2[mf] = V32[r + col + 4];    va3[mf] = V32[r + 2080 + col + 4];
                }
#pragma unroll
                for (int j = 0; j < 4; j++) {
                    int nt16 = nq * 4 + j;
                    uint2 bg = __ldg(((const uint2*)g_GVf) +
                                     ((h * 4 + ks) * 16 + nt16) * 32 + lane);
                    uint2 bv = __ldg(((const uint2*)g_GVf) +
                                     (((8 + h) * 4 + ks) * 16 + nt16) * 32 + lane);
#pragma unroll
                    for (int mf = 0; mf < 2; mf++) {
                        mma_tf32(ag[mf][j],  ua0[mf], ua1[mf], ua2[mf], ua3[mf], bg.x, bg.y);
                        mma_tf32(av4[mf][j], va0[mf], va1[mf], va2[mf], va3[mf], bv.x, bv.y);
                    }
                }
            }
#pragma unroll
            for (int j = 0; j < 4; j++) {
                int c = nq * 32 + j * 8 + 2 * t;
                float2 bias = __ldg((const float2*)(act_bias + h * 128 + c));
#pragma unroll
                for (int mf = 0; mf < 2; mf++) {
                    int r = (mf * 16 + g) * 132;
                    float o0 = fminf(fmaxf(sp(ag[mf][j].x + bias.x), CLIP_LO), CLIP_HI) * av4[mf][j].x;
                    float o1 = fminf(fmaxf(sp(ag[mf][j].y + bias.y), CLIP_LO), CLIP_HI) * av4[mf][j].y;
                    float o2 = fminf(fmaxf(sp(ag[mf][j].z + bias.x), CLIP_LO), CLIP_HI) * av4[mf][j].z;
                    float o3 = fminf(fmaxf(sp(ag[mf][j].w + bias.y), CLIP_LO), CLIP_HI) * av4[mf][j].w;
                    avv[r + c + 0]        = tf32r(o0);
                    avv[r + c + 1]        = tf32r(o1);
                    avv[r + 1056 + c + 0] = tf32r(o2);
                    avv[r + 1056 + c + 1] = tf32r(o3);
                }
            }
        }
        __syncthreads();

        // --- Stage D: 8 warps = 2 heads x 4 col8 ---
        {
            const int sub = wid >> 2;
            const int c8  = wid & 3;
            const int h   = hp * 2 + sub;
            const unsigned* AV = (const unsigned*)(avv_s + sub * (32 * 132));
            float4 dacc[2];
#pragma unroll
            for (int mf = 0; mf < 2; mf++) dacc[mf] = make_float4(0.f, 0.f, 0.f, 0.f);
#pragma unroll
            for (int ks = 0; ks < 16; ks++) {
                int kc = ks * 8 + t;
                uint2 bb = __ldg(((const uint2*)g_Pf) +
                                 ((h * 16 + ks) * 4 + c8) * 32 + lane);
#pragma unroll
                for (int mf = 0; mf < 2; mf++) {
                    int r = (mf * 16 + g) * 132;
                    mma_tf32(dacc[mf], AV[r + kc], AV[r + 1056 + kc],
                             AV[r + kc + 4], AV[r + 1056 + kc + 4], bb.x, bb.y);
                }
            }
            int col = h * 32 + c8 * 8 + 2 * t;
#pragma unroll
            for (int mf = 0; mf < 2; mf++) {
                int row0 = nb + mf * 16 + g;
                if (row0 < N_NODES)
                    *(float2*)&out[(size_t)row0 * WIDTH + col] =
                        make_float2(dacc[mf].x, dacc[mf].y);
                if (row0 + 8 < N_NODES)
                    *(float2*)&out[(size_t)(row0 + 8) * WIDTH + col] =
                        make_float2(dacc[mf].z, dacc[mf].w);
            }
        }
        __syncthreads();
    }
}

// ---------------------------------------------------------------------------
// Launch
// ---------------------------------------------------------------------------
extern "C" void kernel_launch(void* const* d_in, const int* in_sizes, int n_in,
                              void* d_out, int out_size) {
    const float* x            = (const float*)d_in[0];
    const int*   deg          = (const int*)  d_in[1];
    const int*   edge_idx     = (const int*)  d_in[2];
    const int*   edge_attr    = (const int*)  d_in[3];
    const float* node_elec    = (const float*)d_in[4];
    const float* lora_down    = (const float*)d_in[5];
    const float* lora_up      = (const float*)d_in[6];
    const float* emb_edge     = (const float*)d_in[7];
    const float* moa_w        = (const float*)d_in[8];
    const float* moa_s        = (const float*)d_in[9];
    const float* elec_lin     = (const float*)d_in[10];
    const float* emb_deg      = (const float*)d_in[11];
    const float* lin_pre      = (const float*)d_in[12];
    const float* gate_lin     = (const float*)d_in[13];
    const float* gate_kernel  = (const float*)d_in[14];
    const float* value_lin    = (const float*)d_in[15];
    const float* value_kernel = (const float*)d_in[16];
    const float* act_bias     = (const float*)d_in[17];
    const float* post_kernel  = (const float*)d_in[18];
    float* out = (float*)d_out;

    size_t ism = (size_t)32 * 260 * sizeof(float);   // 33280 B
    init_kernel<<<1875 + 1024, 256, ism>>>(x, lora_down);

    work_kernel<<<8028, 256>>>(
        x, edge_idx, edge_attr, node_elec,
        emb_edge, moa_w, moa_s, elec_lin,
        lin_pre, lora_up, gate_lin, value_lin,
        gate_kernel, value_kernel, post_kernel);

    size_t nsm = ((size_t)32 * 292 + 2 * 32 * 260) * sizeof(float);  // 103936 B
    cudaFuncSetAttribute(node_kernel,
                         cudaFuncAttributeMaxDynamicSharedMemorySize, (int)nsm);
    node_kernel<<<(N_NODES + MTILE - 1) / MTILE, 256, nsm>>>(
        x, deg, emb_deg, act_bias, out);
}